// round 2
// baseline (speedup 1.0000x reference)
#include <cuda_runtime.h>
#include <math.h>

// ---------------- problem constants ----------------
#define BB   128      // batch
#define TT   512      // triples per dialogue
#define LQ   256      // query length
#define NN   256      // nodes per dialogue
#define DN   100      // node dim
#define DH   300      // hidden dim
#define EPS  1e-5f

#define M_BT (BB*TT)          // 65536
#define M_BN (BB*NN)          // 32768

// ---------------- device scratch (static globals; no allocation) ----------------
// g_big is time-shared: gi (steps 3-4) and scores (steps 6-7) never coexist.
__device__ float g_trimean[(long)M_BT * DN];          //  26 MB
__device__ float g_x      [(long)M_BT * DH];          //  79 MB
__device__ float g_big    [(long)M_BT * 3 * DH];      // 236 MB (gi, later scores)
__device__ float g_hidden [(long)M_BT * 2 * DH];      // 157 MB
__device__ float g_hid    [(long)M_BT * DH];          //  79 MB (overlays g_trimean lifetime-wise but kept separate for safety)
__device__ float g_alpha  [(long)BB * TT];
__device__ float g_zero_bias[1024];                   // zero-initialized

// ---------------- generic tiled SGEMM: C[M,N] = A[M,K] * B[N,K]^T + bias ----------------
// BM=128, BN=64, BK=16, TM=8, TN=4, 256 threads.
template<bool TANH>
__global__ void gemm_bias_kernel(
    const float* __restrict__ A, const float* __restrict__ Bm,
    const float* __restrict__ bias, float* __restrict__ C,
    int M, int N, int K,
    long strideA, long strideB, long strideC)
{
    const int BM = 128, BN = 64, BK = 16, TM = 8, TN = 4;
    __shared__ float As[BK][BM];
    __shared__ float Bs[BK][BN];

    const int batch = blockIdx.z;
    A  += (long)batch * strideA;
    Bm += (long)batch * strideB;
    C  += (long)batch * strideC;

    const int tid  = threadIdx.x;            // 256
    const int tcol = tid % (BN / TN);        // 0..15
    const int trow = tid / (BN / TN);        // 0..15
    const int rowBase = blockIdx.x * BM;
    const int colBase = blockIdx.y * BN;

    float acc[TM][TN];
    #pragma unroll
    for (int i = 0; i < TM; i++)
        #pragma unroll
        for (int j = 0; j < TN; j++) acc[i][j] = 0.f;

    for (int k0 = 0; k0 < K; k0 += BK) {
        // Load A tile (BM x BK = 2048 elems, 8 per thread)
        #pragma unroll
        for (int i = tid; i < BM * BK; i += 256) {
            int r = i / BK, c = i % BK;
            int gr = rowBase + r, gk = k0 + c;
            As[c][r] = (gr < M && gk < K) ? A[(long)gr * K + gk] : 0.f;
        }
        // Load B tile (BN x BK = 1024 elems, 4 per thread)
        #pragma unroll
        for (int i = tid; i < BN * BK; i += 256) {
            int r = i / BK, c = i % BK;
            int gn = colBase + r, gk = k0 + c;
            Bs[c][r] = (gn < N && gk < K) ? Bm[(long)gn * K + gk] : 0.f;
        }
        __syncthreads();

        #pragma unroll
        for (int kk = 0; kk < BK; kk++) {
            float a[TM], b[TN];
            #pragma unroll
            for (int i = 0; i < TM; i++) a[i] = As[kk][trow * TM + i];
            #pragma unroll
            for (int j = 0; j < TN; j++) b[j] = Bs[kk][tcol * TN + j];
            #pragma unroll
            for (int i = 0; i < TM; i++)
                #pragma unroll
                for (int j = 0; j < TN; j++)
                    acc[i][j] = fmaf(a[i], b[j], acc[i][j]);
        }
        __syncthreads();
    }

    #pragma unroll
    for (int i = 0; i < TM; i++) {
        int gr = rowBase + trow * TM + i;
        if (gr >= M) continue;
        #pragma unroll
        for (int j = 0; j < TN; j++) {
            int gc = colBase + tcol * TN + j;
            if (gc >= N) continue;
            float v = acc[i][j] + bias[gc];
            if (TANH) v = tanhf(v);
            C[(long)gr * N + gc] = v;
        }
    }
}

// ---------------- gather + mean of head/tail node vectors ----------------
__global__ void gather_mean_kernel(const float* __restrict__ nodes,
                                   const int* __restrict__ trip,
                                   float* __restrict__ out)
{
    long idx = (long)blockIdx.x * blockDim.x + threadIdx.x;
    long total = (long)M_BT * DN;
    if (idx >= total) return;
    int d  = (int)(idx % DN);
    long bt = idx / DN;
    int b = (int)(bt / TT);
    int t = (int)(bt % TT);
    int h  = trip[((long)b * TT + t) * 3 + 0];
    int tl = trip[((long)b * TT + t) * 3 + 2];
    float vh = nodes[((long)b * NN + h)  * DN + d];
    float vt = nodes[((long)b * NN + tl) * DN + d];
    out[idx] = 0.5f * (vh + vt);
}

// ---------------- GRU gate activation (h0 = 0) ----------------
__global__ void gru_act_kernel(const float* __restrict__ gi,
                               const float* __restrict__ b_hh,
                               float* __restrict__ h_out, int ldh)
{
    long idx = (long)blockIdx.x * blockDim.x + threadIdx.x;
    long total = (long)M_BT * DH;
    if (idx >= total) return;
    long i = idx / DH;
    int  j = (int)(idx % DH);
    const float* gir = gi + i * (3 * DH);
    float r = 1.f / (1.f + expf(-(gir[j]          + b_hh[j])));
    float z = 1.f / (1.f + expf(-(gir[DH + j]     + b_hh[DH + j])));
    float n = tanhf(gir[2 * DH + j] + r * b_hh[2 * DH + j]);
    h_out[i * ldh + j] = (1.f - z) * n;
}

// ---------------- per-batch softmax over T, accumulate alpha ----------------
// One block per batch, 512 threads (= TT). Loops over the Lq rows; each row:
// block max, exp, block sum, accumulate e/sum into per-thread alpha.
__global__ void softmax_alpha_kernel(const float* __restrict__ S,
                                     float* __restrict__ alpha)
{
    int b = blockIdx.x;
    int t = threadIdx.x;          // 512 threads = TT
    __shared__ float red[32];
    float acc = 0.f;
    const float* Sb = S + (long)b * LQ * TT;
    for (int l = 0; l < LQ; l++) {
        float s = Sb[(long)l * TT + t];
        float m = s;
        #pragma unroll
        for (int o = 16; o > 0; o >>= 1) m = fmaxf(m, __shfl_xor_sync(0xffffffffu, m, o));
        if ((t & 31) == 0) red[t >> 5] = m;
        __syncthreads();
        float bm = red[0];
        #pragma unroll
        for (int w = 1; w < 16; w++) bm = fmaxf(bm, red[w]);
        __syncthreads();
        float e = expf(s - bm);
        float sm = e;
        #pragma unroll
        for (int o = 16; o > 0; o >>= 1) sm += __shfl_xor_sync(0xffffffffu, sm, o);
        if ((t & 31) == 0) red[t >> 5] = sm;
        __syncthreads();
        float tot = 0.f;
        #pragma unroll
        for (int w = 0; w < 16; w++) tot += red[w];
        __syncthreads();
        acc += e / tot;
    }
    alpha[(long)b * TT + t] = acc;
}

// ---------------- rep = alpha @ hid, then LayerNorm -> path_feature ----------------
__global__ void rep_ln_kernel(const float* __restrict__ hid,
                              const float* __restrict__ alpha,
                              const float* __restrict__ gamma,
                              const float* __restrict__ beta,
                              float* __restrict__ out)
{
    int b = blockIdx.x;
    int tid = threadIdx.x;        // 512
    __shared__ float a_s[TT];
    __shared__ float r_s[DH];
    __shared__ float red[32];
    a_s[tid] = alpha[(long)b * TT + tid];
    __syncthreads();
    if (tid < DH) {
        const float* hb = hid + (long)b * TT * DH;
        float v = 0.f;
        for (int t = 0; t < TT; t++) v = fmaf(a_s[t], hb[(long)t * DH + tid], v);
        r_s[tid] = v;
    }
    __syncthreads();
    float p  = (tid < DH) ? r_s[tid] : 0.f;
    float p2 = p * p;
    #pragma unroll
    for (int o = 16; o > 0; o >>= 1) {
        p  += __shfl_xor_sync(0xffffffffu, p,  o);
        p2 += __shfl_xor_sync(0xffffffffu, p2, o);
    }
    if ((tid & 31) == 0) { red[tid >> 5] = p; red[16 + (tid >> 5)] = p2; }
    __syncthreads();
    float mean = 0.f, m2 = 0.f;
    #pragma unroll
    for (int w = 0; w < 16; w++) { mean += red[w]; m2 += red[16 + w]; }
    mean /= (float)DH; m2 /= (float)DH;
    float var = m2 - mean * mean;
    if (tid < DH)
        out[(long)b * DH + tid] =
            (r_s[tid] - mean) * rsqrtf(var + EPS) * gamma[tid] + beta[tid];
}

// ---------------- zero-fill (mask region) ----------------
__global__ void zero_kernel(float* __restrict__ p, long n)
{
    long i = (long)blockIdx.x * blockDim.x + threadIdx.x;
    if (i < n) p[i] = 0.f;
}

// ---------------- host launcher ----------------
extern "C" void kernel_launch(void* const* d_in, const int* in_sizes, int n_in,
                              void* d_out, int out_size)
{
    const float* nodes   = (const float*)d_in[0];
    const float* ctx     = (const float*)d_in[1];
    const int*   trip    = (const int*)  d_in[2];
    // d_in[3] = node_number (compile-time constant NN = 256)
    const float* W_mean  = (const float*)d_in[4];
    const float* b_mean  = (const float*)d_in[5];
    const float* W_ih_f  = (const float*)d_in[6];
    const float* b_ih_f  = (const float*)d_in[7];
    const float* b_hh_f  = (const float*)d_in[8];
    const float* W_ih_b  = (const float*)d_in[9];
    const float* b_ih_b  = (const float*)d_in[10];
    const float* b_hh_b  = (const float*)d_in[11];
    const float* W_out   = (const float*)d_in[12];
    const float* b_out   = (const float*)d_in[13];
    const float* W_node  = (const float*)d_in[14];
    const float* b_node  = (const float*)d_in[15];
    const float* gamma   = (const float*)d_in[16];
    const float* beta    = (const float*)d_in[17];
    float* out = (float*)d_out;

    float *p_trimean, *p_x, *p_big, *p_hidden, *p_hid, *p_alpha, *p_zb;
    cudaGetSymbolAddress((void**)&p_trimean, g_trimean);
    cudaGetSymbolAddress((void**)&p_x,       g_x);
    cudaGetSymbolAddress((void**)&p_big,     g_big);
    cudaGetSymbolAddress((void**)&p_hidden,  g_hidden);
    cudaGetSymbolAddress((void**)&p_hid,     g_hid);
    cudaGetSymbolAddress((void**)&p_alpha,   g_alpha);
    cudaGetSymbolAddress((void**)&p_zb,      g_zero_bias);

    float* p_gi     = p_big;   // [M_BT, 900]   steps 3-4
    float* p_scores = p_big;   // [B, LQ, TT]   steps 6-7 (disjoint lifetime)

    // 1) tri_mean gather: 0.5*(nodes[head] + nodes[tail])
    {
        long total = (long)M_BT * DN;
        gather_mean_kernel<<<(unsigned)((total + 255) / 256), 256>>>(nodes, trip, p_trimean);
    }
    // 2) x = tri_mean @ W_mean^T + b_mean      [65536,300] K=100
    {
        dim3 g(M_BT / 128, (DH + 63) / 64, 1);
        gemm_bias_kernel<false><<<g, 256>>>(p_trimean, W_mean, b_mean, p_x,
                                            M_BT, DH, DN, 0, 0, 0);
    }
    // 3) forward GRU: gi = x @ W_ih_f^T + b_ih_f, then gate activation
    {
        dim3 g(M_BT / 128, (3 * DH + 63) / 64, 1);
        gemm_bias_kernel<false><<<g, 256>>>(p_x, W_ih_f, b_ih_f, p_gi,
                                            M_BT, 3 * DH, DH, 0, 0, 0);
        long total = (long)M_BT * DH;
        gru_act_kernel<<<(unsigned)((total + 255) / 256), 256>>>(p_gi, b_hh_f,
                                                                 p_hidden, 2 * DH);
    }
    // 4) backward GRU (reuses gi scratch)
    {
        dim3 g(M_BT / 128, (3 * DH + 63) / 64, 1);
        gemm_bias_kernel<false><<<g, 256>>>(p_x, W_ih_b, b_ih_b, p_gi,
                                            M_BT, 3 * DH, DH, 0, 0, 0);
        long total = (long)M_BT * DH;
        gru_act_kernel<<<(unsigned)((total + 255) / 256), 256>>>(p_gi, b_hh_b,
                                                                 p_hidden + DH, 2 * DH);
    }
    // 5) hid_ = tanh(hidden @ W_out^T + b_out)  [65536,300] K=600
    {
        dim3 g(M_BT / 128, (DH + 63) / 64, 1);
        gemm_bias_kernel<true><<<g, 256>>>(p_hidden, W_out, b_out, p_hid,
                                           M_BT, DH, 2 * DH, 0, 0, 0);
    }
    // 6) scores[b] = ctx[b] @ hid_[b]^T   (batched: M=256, N=512, K=300)
    {
        dim3 g(LQ / 128, TT / 64, BB);
        gemm_bias_kernel<false><<<g, 256>>>(ctx, p_hid, p_zb, p_scores,
                                            LQ, TT, DH,
                                            (long)LQ * DH, (long)TT * DH,
                                            (long)LQ * TT);
    }
    // 7) softmax over T, sum over Lq -> alpha [B,T]
    softmax_alpha_kernel<<<BB, TT>>>(p_scores, p_alpha);
    // 8) rep = alpha @ hid_, LayerNorm -> path_feature (out offset 0)
    rep_ln_kernel<<<BB, TT>>>(p_hid, p_alpha, gamma, beta, out);
    // 9) node_feature = nodes @ W_node^T + b_node -> out offset B*DH
    {
        dim3 g(M_BN / 128, (DH + 63) / 64, 1);
        gemm_bias_kernel<false><<<g, 256>>>(nodes, W_node, b_node,
                                            out + (long)BB * DH,
                                            M_BN, DH, DN, 0, 0, 0);
    }
    // 10) node_mask (all False) -> zeros, if the output buffer includes it
    {
        long mask_off = (long)BB * DH + (long)M_BN * DH;   // 9,868,800
        long mask_n   = (long)BB * NN;                     // 32,768
        if ((long)out_size >= mask_off + mask_n) {
            zero_kernel<<<(unsigned)((mask_n + 255) / 256), 256>>>(out + mask_off, mask_n);
        }
    }
}

// round 3
// speedup vs baseline: 1.1511x; 1.1511x over previous
#include <cuda_runtime.h>
#include <math.h>

// ---------------- problem constants ----------------
#define BB   128      // batch
#define TT   512      // triples per dialogue
#define LQ   256      // query length
#define NN   256      // nodes per dialogue
#define DN   100      // node dim
#define DH   300      // hidden dim
#define EPS  1e-5f

#define M_BT (BB*TT)          // 65536
#define M_BN (BB*NN)          // 32768

// ---------------- device scratch (static globals; no allocation) ----------------
__device__ float g_trimean[(long)M_BT * DN];          //  26 MB
__device__ float g_x      [(long)M_BT * DH];          //  79 MB
__device__ float g_big    [(long)M_BT * 6 * DH];      // 472 MB (gi both dirs [M,1800]; later scores [B,LQ,TT])
__device__ float g_hidden [(long)M_BT * 2 * DH];      // 157 MB
__device__ float g_hid    [(long)M_BT * DH];          //  79 MB
__device__ float g_alpha  [(long)BB * TT];
__device__ float g_Wih    [2 * 3 * DH * DH];          // concat W_ih_f ; W_ih_b  [1800,300]
__device__ float g_bih    [2 * 3 * DH];               // concat b_ih_f ; b_ih_b  [1800]
__device__ float g_zero_bias[1024];                   // zero-initialized

// ---------------- tiled SGEMM v2: C[M,N] = A[M,K] * B[N,K]^T + bias ----------------
// BM=128, BN=128, BK=16, TM=8, TN=8, 256 threads. 1 B/FMA smem demand.
template<bool TANH>
__global__ void __launch_bounds__(256)
gemm128_kernel(const float* __restrict__ A, const float* __restrict__ Bm,
               const float* __restrict__ bias, float* __restrict__ C,
               int M, int N, int K,
               long strideA, long strideB, long strideC)
{
    const int BM = 128, BN = 128, BK = 16, TM = 8, TN = 8;
    __shared__ float As[BK][BM];
    __shared__ float Bs[BK][BN];

    const int batch = blockIdx.z;
    A  += (long)batch * strideA;
    Bm += (long)batch * strideB;
    C  += (long)batch * strideC;

    const int tid  = threadIdx.x;            // 0..255
    const int tcol = tid % 16;               // 0..15 -> N sub-tile
    const int trow = tid / 16;               // 0..15 -> M sub-tile
    const int rowBase = blockIdx.x * BM;
    const int colBase = blockIdx.y * BN;

    float acc[TM][TN];
    #pragma unroll
    for (int i = 0; i < TM; i++)
        #pragma unroll
        for (int j = 0; j < TN; j++) acc[i][j] = 0.f;

    for (int k0 = 0; k0 < K; k0 += BK) {
        // Load A tile (128x16 = 2048 elems, 8 scalar loads/thread), store transposed
        #pragma unroll
        for (int it = 0; it < 8; it++) {
            int i = tid + it * 256;
            int r = i >> 4, c = i & 15;
            int gr = rowBase + r, gk = k0 + c;
            As[c][r] = (gr < M && gk < K) ? A[(long)gr * K + gk] : 0.f;
        }
        // Load B tile (128x16), store transposed
        #pragma unroll
        for (int it = 0; it < 8; it++) {
            int i = tid + it * 256;
            int r = i >> 4, c = i & 15;
            int gn = colBase + r, gk = k0 + c;
            Bs[c][r] = (gn < N && gk < K) ? Bm[(long)gn * K + gk] : 0.f;
        }
        __syncthreads();

        #pragma unroll
        for (int kk = 0; kk < BK; kk++) {
            float a[TM], b[TN];
            #pragma unroll
            for (int i = 0; i < TM; i++) a[i] = As[kk][trow * TM + i];
            #pragma unroll
            for (int j = 0; j < TN; j++) b[j] = Bs[kk][tcol * TN + j];
            #pragma unroll
            for (int i = 0; i < TM; i++)
                #pragma unroll
                for (int j = 0; j < TN; j++)
                    acc[i][j] = fmaf(a[i], b[j], acc[i][j]);
        }
        __syncthreads();
    }

    #pragma unroll
    for (int i = 0; i < TM; i++) {
        int gr = rowBase + trow * TM + i;
        if (gr >= M) continue;
        #pragma unroll
        for (int j = 0; j < TN; j++) {
            int gc = colBase + tcol * TN + j;
            if (gc >= N) continue;
            float v = acc[i][j] + bias[gc];
            if (TANH) v = tanhf(v);
            C[(long)gr * N + gc] = v;
        }
    }
}

// ---------------- gather + mean of head/tail node vectors ----------------
__global__ void gather_mean_kernel(const float* __restrict__ nodes,
                                   const int* __restrict__ trip,
                                   float* __restrict__ out)
{
    long idx = (long)blockIdx.x * blockDim.x + threadIdx.x;
    long total = (long)M_BT * DN;
    if (idx >= total) return;
    int d  = (int)(idx % DN);
    long bt = idx / DN;
    int b = (int)(bt / TT);
    int t = (int)(bt % TT);
    int h  = trip[((long)b * TT + t) * 3 + 0];
    int tl = trip[((long)b * TT + t) * 3 + 2];
    float vh = nodes[((long)b * NN + h)  * DN + d];
    float vt = nodes[((long)b * NN + tl) * DN + d];
    out[idx] = 0.5f * (vh + vt);
}

// ---------------- combined GRU gate activation for both directions (h0=0) ------
// gi: [M_BT, 1800] (fwd gates 0..900, bwd gates 900..1800)
// hidden: [M_BT, 600] (fwd 0..300, bwd 300..600)
__global__ void gru_act2_kernel(const float* __restrict__ gi,
                                const float* __restrict__ b_hh_f,
                                const float* __restrict__ b_hh_b,
                                float* __restrict__ hidden)
{
    long idx = (long)blockIdx.x * blockDim.x + threadIdx.x;
    long total = (long)M_BT * 2 * DH;
    if (idx >= total) return;
    long i = idx / (2 * DH);
    int  c = (int)(idx % (2 * DH));
    int dir = c / DH;
    int j   = c % DH;
    const float* gir = gi + i * (6 * DH) + (long)dir * (3 * DH);
    const float* bh  = dir ? b_hh_b : b_hh_f;
    float r = 1.f / (1.f + expf(-(gir[j]          + bh[j])));
    float z = 1.f / (1.f + expf(-(gir[DH + j]     + bh[DH + j])));
    float n = tanhf(gir[2 * DH + j] + r * bh[2 * DH + j]);
    hidden[i * (2 * DH) + c] = (1.f - z) * n;
}

// ---------------- per-row softmax + atomic alpha accumulation ----------------
// grid (LQ, BB), block 512 (= TT). Each block: one (b,l) score row.
__global__ void softmax_row_kernel(const float* __restrict__ S,
                                   float* __restrict__ alpha)
{
    int l = blockIdx.x, b = blockIdx.y;
    int t = threadIdx.x;                 // 0..511
    __shared__ float red[16];
    __shared__ float bcast;
    const float* row = S + ((long)b * LQ + l) * TT;
    float s = row[t];

    // block max
    float m = s;
    #pragma unroll
    for (int o = 16; o > 0; o >>= 1) m = fmaxf(m, __shfl_xor_sync(0xffffffffu, m, o));
    if ((t & 31) == 0) red[t >> 5] = m;
    __syncthreads();
    if (t < 16) {
        float v = red[t];
        #pragma unroll
        for (int o = 8; o > 0; o >>= 1) v = fmaxf(v, __shfl_xor_sync(0xffffu, v, o));
        if (t == 0) bcast = v;
    }
    __syncthreads();
    float bm = bcast;

    float e = expf(s - bm);
    // block sum
    float sm = e;
    #pragma unroll
    for (int o = 16; o > 0; o >>= 1) sm += __shfl_xor_sync(0xffffffffu, sm, o);
    if ((t & 31) == 0) red[t >> 5] = sm;
    __syncthreads();
    if (t < 16) {
        float v = red[t];
        #pragma unroll
        for (int o = 8; o > 0; o >>= 1) v += __shfl_xor_sync(0xffffu, v, o);
        if (t == 0) bcast = v;
    }
    __syncthreads();
    float tot = bcast;

    atomicAdd(&alpha[(long)b * TT + t], e / tot);
}

// ---------------- rep = alpha @ hid, then LayerNorm -> path_feature ----------------
__global__ void rep_ln_kernel(const float* __restrict__ hid,
                              const float* __restrict__ alpha,
                              const float* __restrict__ gamma,
                              const float* __restrict__ beta,
                              float* __restrict__ out)
{
    int b = blockIdx.x;
    int tid = threadIdx.x;        // 512
    __shared__ float a_s[TT];
    __shared__ float r_s[DH];
    __shared__ float red[32];
    a_s[tid] = alpha[(long)b * TT + tid];
    __syncthreads();
    if (tid < DH) {
        const float* hb = hid + (long)b * TT * DH;
        float v0 = 0.f, v1 = 0.f, v2 = 0.f, v3 = 0.f;
        #pragma unroll 1
        for (int t = 0; t < TT; t += 4) {
            v0 = fmaf(a_s[t + 0], hb[(long)(t + 0) * DH + tid], v0);
            v1 = fmaf(a_s[t + 1], hb[(long)(t + 1) * DH + tid], v1);
            v2 = fmaf(a_s[t + 2], hb[(long)(t + 2) * DH + tid], v2);
            v3 = fmaf(a_s[t + 3], hb[(long)(t + 3) * DH + tid], v3);
        }
        r_s[tid] = (v0 + v1) + (v2 + v3);
    }
    __syncthreads();
    float p  = (tid < DH) ? r_s[tid] : 0.f;
    float p2 = p * p;
    #pragma unroll
    for (int o = 16; o > 0; o >>= 1) {
        p  += __shfl_xor_sync(0xffffffffu, p,  o);
        p2 += __shfl_xor_sync(0xffffffffu, p2, o);
    }
    if ((tid & 31) == 0) { red[tid >> 5] = p; red[16 + (tid >> 5)] = p2; }
    __syncthreads();
    float mean = 0.f, m2 = 0.f;
    #pragma unroll
    for (int w = 0; w < 16; w++) { mean += red[w]; m2 += red[16 + w]; }
    mean /= (float)DH; m2 /= (float)DH;
    float var = m2 - mean * mean;
    if (tid < DH)
        out[(long)b * DH + tid] =
            (r_s[tid] - mean) * rsqrtf(var + EPS) * gamma[tid] + beta[tid];
}

// ---------------- zero-fill ----------------
__global__ void zero_kernel(float* __restrict__ p, long n)
{
    long i = (long)blockIdx.x * blockDim.x + threadIdx.x;
    if (i < n) p[i] = 0.f;
}

// ---------------- host launcher ----------------
extern "C" void kernel_launch(void* const* d_in, const int* in_sizes, int n_in,
                              void* d_out, int out_size)
{
    const float* nodes   = (const float*)d_in[0];
    const float* ctx     = (const float*)d_in[1];
    const int*   trip    = (const int*)  d_in[2];
    // d_in[3] = node_number (compile-time constant NN = 256)
    const float* W_mean  = (const float*)d_in[4];
    const float* b_mean  = (const float*)d_in[5];
    const float* W_ih_f  = (const float*)d_in[6];
    const float* b_ih_f  = (const float*)d_in[7];
    const float* b_hh_f  = (const float*)d_in[8];
    const float* W_ih_b  = (const float*)d_in[9];
    const float* b_ih_b  = (const float*)d_in[10];
    const float* b_hh_b  = (const float*)d_in[11];
    const float* W_out   = (const float*)d_in[12];
    const float* b_out   = (const float*)d_in[13];
    const float* W_node  = (const float*)d_in[14];
    const float* b_node  = (const float*)d_in[15];
    const float* gamma   = (const float*)d_in[16];
    const float* beta    = (const float*)d_in[17];
    float* out = (float*)d_out;

    float *p_trimean, *p_x, *p_big, *p_hidden, *p_hid, *p_alpha, *p_Wih, *p_bih, *p_zb;
    cudaGetSymbolAddress((void**)&p_trimean, g_trimean);
    cudaGetSymbolAddress((void**)&p_x,       g_x);
    cudaGetSymbolAddress((void**)&p_big,     g_big);
    cudaGetSymbolAddress((void**)&p_hidden,  g_hidden);
    cudaGetSymbolAddress((void**)&p_hid,     g_hid);
    cudaGetSymbolAddress((void**)&p_alpha,   g_alpha);
    cudaGetSymbolAddress((void**)&p_Wih,     g_Wih);
    cudaGetSymbolAddress((void**)&p_bih,     g_bih);
    cudaGetSymbolAddress((void**)&p_zb,      g_zero_bias);

    float* p_gi     = p_big;   // [M_BT, 1800]  GRU phase
    float* p_scores = p_big;   // [B, LQ, TT]   attention phase (disjoint lifetime)

    // 0) concat GRU weights/biases into scratch (d2d async copies; capture-legal)
    cudaMemcpyAsync(p_Wih,                W_ih_f, (size_t)3 * DH * DH * 4, cudaMemcpyDeviceToDevice);
    cudaMemcpyAsync(p_Wih + 3 * DH * DH,  W_ih_b, (size_t)3 * DH * DH * 4, cudaMemcpyDeviceToDevice);
    cudaMemcpyAsync(p_bih,                b_ih_f, (size_t)3 * DH * 4,      cudaMemcpyDeviceToDevice);
    cudaMemcpyAsync(p_bih + 3 * DH,       b_ih_b, (size_t)3 * DH * 4,      cudaMemcpyDeviceToDevice);

    // 1) tri_mean gather: 0.5*(nodes[head] + nodes[tail])
    {
        long total = (long)M_BT * DN;
        gather_mean_kernel<<<(unsigned)((total + 255) / 256), 256>>>(nodes, trip, p_trimean);
    }
    // 2) x = tri_mean @ W_mean^T + b_mean      [65536,300] K=100
    {
        dim3 g(M_BT / 128, (DH + 127) / 128, 1);
        gemm128_kernel<false><<<g, 256>>>(p_trimean, W_mean, b_mean, p_x,
                                          M_BT, DH, DN, 0, 0, 0);
    }
    // 3) both GRU directions in one GEMM: gi = x @ Wih^T + bih   [65536,1800] K=300
    {
        dim3 g(M_BT / 128, (6 * DH + 127) / 128, 1);
        gemm128_kernel<false><<<g, 256>>>(p_x, p_Wih, p_bih, p_gi,
                                          M_BT, 6 * DH, DH, 0, 0, 0);
    }
    // 4) combined gate activation -> hidden [65536,600]
    {
        long total = (long)M_BT * 2 * DH;
        gru_act2_kernel<<<(unsigned)((total + 255) / 256), 256>>>(p_gi, b_hh_f, b_hh_b, p_hidden);
    }
    // 5) hid_ = tanh(hidden @ W_out^T + b_out)  [65536,300] K=600
    {
        dim3 g(M_BT / 128, (DH + 127) / 128, 1);
        gemm128_kernel<true><<<g, 256>>>(p_hidden, W_out, b_out, p_hid,
                                         M_BT, DH, 2 * DH, 0, 0, 0);
    }
    // 6) scores[b] = ctx[b] @ hid_[b]^T   (batched: M=256, N=512, K=300)
    {
        dim3 g(LQ / 128, TT / 128, BB);
        gemm128_kernel<false><<<g, 256>>>(ctx, p_hid, p_zb, p_scores,
                                          LQ, TT, DH,
                                          (long)LQ * DH, (long)TT * DH,
                                          (long)LQ * TT);
    }
    // 7) alpha = sum_l softmax_t(scores)  (zero, then atomic accumulation)
    {
        long an = (long)BB * TT;
        zero_kernel<<<(unsigned)((an + 255) / 256), 256>>>(p_alpha, an);
        dim3 g(LQ, BB);
        softmax_row_kernel<<<g, TT>>>(p_scores, p_alpha);
    }
    // 8) rep = alpha @ hid_, LayerNorm -> path_feature (out offset 0)
    rep_ln_kernel<<<BB, TT>>>(p_hid, p_alpha, gamma, beta, out);
    // 9) node_feature = nodes @ W_node^T + b_node -> out offset B*DH
    {
        dim3 g(M_BN / 128, (DH + 127) / 128, 1);
        gemm128_kernel<false><<<g, 256>>>(nodes, W_node, b_node,
                                          out + (long)BB * DH,
                                          M_BN, DH, DN, 0, 0, 0);
    }
    // 10) node_mask (all False) -> zeros, if the output buffer includes it
    {
        long mask_off = (long)BB * DH + (long)M_BN * DH;   // 9,868,800
        long mask_n   = (long)BB * NN;                     // 32,768
        if ((long)out_size >= mask_off + mask_n) {
            zero_kernel<<<(unsigned)((mask_n + 255) / 256), 256>>>(out + mask_off, mask_n);
        }
    }
}

// round 4
// speedup vs baseline: 1.8715x; 1.6258x over previous
#include <cuda_runtime.h>
#include <math.h>

// ---------------- problem constants ----------------
#define BB   128      // batch
#define TT   512      // triples per dialogue
#define LQ   256      // query length
#define NN   256      // nodes per dialogue
#define DN   100      // node dim
#define DH   300      // hidden dim
#define EPS  1e-5f

#define M_BT (BB*TT)          // 65536
#define M_BN (BB*NN)          // 32768

// ---------------- device scratch (static globals; no allocation) ----------------
__device__ float g_trimean[(long)M_BT * DN];          //  26 MB
__device__ float g_x      [(long)M_BT * DH];          //  79 MB
__device__ float g_big    [(long)M_BT * 6 * DH];      // 472 MB (gi [M,1800]; later scores [B,LQ,TT])
__device__ float g_hidden [(long)M_BT * 2 * DH];      // 157 MB
__device__ float g_hid    [(long)M_BT * DH];          //  79 MB
__device__ float g_alpha  [(long)BB * TT];
__device__ float g_Wih    [2 * 3 * DH * DH];          // concat W_ih_f ; W_ih_b  [1800,300]
__device__ float g_bih    [2 * 3 * DH];               // concat b_ih_f ; b_ih_b  [1800]
__device__ float g_zero_bias[1024];                   // zero-initialized

// ---------------- tiled SGEMM v3: C[M,N] = A[M,K] * B[N,K]^T + bias ----------------
// BM=BN=128, BK=16, TM=TN=8, 256 threads.
// float4 LDG, transposed STS with +4 pad (<=2-way conflicts), float4 LDS frags,
// float4 epilogue. M assumed multiple of 128 by callers; N,K arbitrary (mult of 4).
template<bool TANH>
__global__ void __launch_bounds__(256)
gemm128_kernel(const float* __restrict__ A, const float* __restrict__ Bm,
               const float* __restrict__ bias, float* __restrict__ C,
               int M, int N, int K,
               long strideA, long strideB, long strideC)
{
    const int BM = 128, BN = 128, BK = 16;
    __shared__ float As[BK][BM + 4];   // 132 floats/row: 16B-aligned rows
    __shared__ float Bs[BK][BN + 4];

    const int batch = blockIdx.z;
    A  += (long)batch * strideA;
    Bm += (long)batch * strideB;
    C  += (long)batch * strideC;

    const int tid  = threadIdx.x;            // 0..255
    const int tcol = tid % 16;
    const int trow = tid / 16;
    const int rowBase = blockIdx.x * BM;
    const int colBase = blockIdx.y * BN;

    float acc[8][8];
    #pragma unroll
    for (int i = 0; i < 8; i++)
        #pragma unroll
        for (int j = 0; j < 8; j++) acc[i][j] = 0.f;

    for (int k0 = 0; k0 < K; k0 += BK) {
        // ---- A tile: 128x16 = 512 float4, 2 per thread ----
        #pragma unroll
        for (int it = 0; it < 2; it++) {
            int idx = tid + it * 256;
            int r = idx >> 2;            // 0..127
            int q = idx & 3;             // 0..3
            int gr = rowBase + r;
            int gk = k0 + q * 4;
            float4 v = make_float4(0.f, 0.f, 0.f, 0.f);
            if (gr < M) {
                if (gk + 3 < K) {
                    v = *reinterpret_cast<const float4*>(&A[(long)gr * K + gk]);
                } else {
                    float t0 = (gk + 0 < K) ? A[(long)gr * K + gk + 0] : 0.f;
                    float t1 = (gk + 1 < K) ? A[(long)gr * K + gk + 1] : 0.f;
                    float t2 = (gk + 2 < K) ? A[(long)gr * K + gk + 2] : 0.f;
                    float t3 = (gk + 3 < K) ? A[(long)gr * K + gk + 3] : 0.f;
                    v = make_float4(t0, t1, t2, t3);
                }
            }
            As[q * 4 + 0][r] = v.x;
            As[q * 4 + 1][r] = v.y;
            As[q * 4 + 2][r] = v.z;
            As[q * 4 + 3][r] = v.w;
        }
        // ---- B tile ----
        #pragma unroll
        for (int it = 0; it < 2; it++) {
            int idx = tid + it * 256;
            int r = idx >> 2;
            int q = idx & 3;
            int gn = colBase + r;
            int gk = k0 + q * 4;
            float4 v = make_float4(0.f, 0.f, 0.f, 0.f);
            if (gn < N) {
                if (gk + 3 < K) {
                    v = *reinterpret_cast<const float4*>(&Bm[(long)gn * K + gk]);
                } else {
                    float t0 = (gk + 0 < K) ? Bm[(long)gn * K + gk + 0] : 0.f;
                    float t1 = (gk + 1 < K) ? Bm[(long)gn * K + gk + 1] : 0.f;
                    float t2 = (gk + 2 < K) ? Bm[(long)gn * K + gk + 2] : 0.f;
                    float t3 = (gk + 3 < K) ? Bm[(long)gn * K + gk + 3] : 0.f;
                    v = make_float4(t0, t1, t2, t3);
                }
            }
            Bs[q * 4 + 0][r] = v.x;
            Bs[q * 4 + 1][r] = v.y;
            Bs[q * 4 + 2][r] = v.z;
            Bs[q * 4 + 3][r] = v.w;
        }
        __syncthreads();

        #pragma unroll
        for (int kk = 0; kk < BK; kk++) {
            float4 a0 = *reinterpret_cast<const float4*>(&As[kk][trow * 8]);
            float4 a1 = *reinterpret_cast<const float4*>(&As[kk][trow * 8 + 4]);
            float4 b0 = *reinterpret_cast<const float4*>(&Bs[kk][tcol * 8]);
            float4 b1 = *reinterpret_cast<const float4*>(&Bs[kk][tcol * 8 + 4]);
            float a[8] = {a0.x, a0.y, a0.z, a0.w, a1.x, a1.y, a1.z, a1.w};
            float b[8] = {b0.x, b0.y, b0.z, b0.w, b1.x, b1.y, b1.z, b1.w};
            #pragma unroll
            for (int i = 0; i < 8; i++)
                #pragma unroll
                for (int j = 0; j < 8; j++)
                    acc[i][j] = fmaf(a[i], b[j], acc[i][j]);
        }
        __syncthreads();
    }

    // ---- epilogue: bias (+tanh), float4 stores ----
    #pragma unroll
    for (int i = 0; i < 8; i++) {
        int gr = rowBase + trow * 8 + i;
        if (gr >= M) continue;
        #pragma unroll
        for (int jj = 0; jj < 2; jj++) {
            int gc = colBase + tcol * 8 + jj * 4;
            if (gc + 3 < N) {
                float4 v;
                v.x = acc[i][jj * 4 + 0] + bias[gc + 0];
                v.y = acc[i][jj * 4 + 1] + bias[gc + 1];
                v.z = acc[i][jj * 4 + 2] + bias[gc + 2];
                v.w = acc[i][jj * 4 + 3] + bias[gc + 3];
                if (TANH) { v.x = tanhf(v.x); v.y = tanhf(v.y); v.z = tanhf(v.z); v.w = tanhf(v.w); }
                *reinterpret_cast<float4*>(&C[(long)gr * N + gc]) = v;
            } else {
                #pragma unroll
                for (int s = 0; s < 4; s++) {
                    int c = gc + s;
                    if (c < N) {
                        float v = acc[i][jj * 4 + s] + bias[c];
                        if (TANH) v = tanhf(v);
                        C[(long)gr * N + c] = v;
                    }
                }
            }
        }
    }
}

// ---------------- gather + mean of head/tail node vectors ----------------
__global__ void gather_mean_kernel(const float* __restrict__ nodes,
                                   const int* __restrict__ trip,
                                   float* __restrict__ out)
{
    long idx = (long)blockIdx.x * blockDim.x + threadIdx.x;
    long total = (long)M_BT * DN;
    if (idx >= total) return;
    int d  = (int)(idx % DN);
    long bt = idx / DN;
    int b = (int)(bt / TT);
    int t = (int)(bt % TT);
    int h  = trip[((long)b * TT + t) * 3 + 0];
    int tl = trip[((long)b * TT + t) * 3 + 2];
    float vh = nodes[((long)b * NN + h)  * DN + d];
    float vt = nodes[((long)b * NN + tl) * DN + d];
    out[idx] = 0.5f * (vh + vt);
}

// ---------------- combined GRU gate activation for both directions (h0=0) ------
__global__ void gru_act2_kernel(const float* __restrict__ gi,
                                const float* __restrict__ b_hh_f,
                                const float* __restrict__ b_hh_b,
                                float* __restrict__ hidden)
{
    long idx = (long)blockIdx.x * blockDim.x + threadIdx.x;
    long total = (long)M_BT * 2 * DH;
    if (idx >= total) return;
    long i = idx / (2 * DH);
    int  c = (int)(idx % (2 * DH));
    int dir = c / DH;
    int j   = c % DH;
    const float* gir = gi + i * (6 * DH) + (long)dir * (3 * DH);
    const float* bh  = dir ? b_hh_b : b_hh_f;
    float r = 1.f / (1.f + expf(-(gir[j]          + bh[j])));
    float z = 1.f / (1.f + expf(-(gir[DH + j]     + bh[DH + j])));
    float n = tanhf(gir[2 * DH + j] + r * bh[2 * DH + j]);
    hidden[i * (2 * DH) + c] = (1.f - z) * n;
}

// ---------------- per-row softmax + atomic alpha accumulation ----------------
__global__ void softmax_row_kernel(const float* __restrict__ S,
                                   float* __restrict__ alpha)
{
    int l = blockIdx.x, b = blockIdx.y;
    int t = threadIdx.x;                 // 0..511
    __shared__ float red[16];
    __shared__ float bcast;
    const float* row = S + ((long)b * LQ + l) * TT;
    float s = row[t];

    float m = s;
    #pragma unroll
    for (int o = 16; o > 0; o >>= 1) m = fmaxf(m, __shfl_xor_sync(0xffffffffu, m, o));
    if ((t & 31) == 0) red[t >> 5] = m;
    __syncthreads();
    if (t < 16) {
        float v = red[t];
        #pragma unroll
        for (int o = 8; o > 0; o >>= 1) v = fmaxf(v, __shfl_xor_sync(0xffffu, v, o));
        if (t == 0) bcast = v;
    }
    __syncthreads();
    float bm = bcast;

    float e = expf(s - bm);
    float sm = e;
    #pragma unroll
    for (int o = 16; o > 0; o >>= 1) sm += __shfl_xor_sync(0xffffffffu, sm, o);
    if ((t & 31) == 0) red[t >> 5] = sm;
    __syncthreads();
    if (t < 16) {
        float v = red[t];
        #pragma unroll
        for (int o = 8; o > 0; o >>= 1) v += __shfl_xor_sync(0xffffu, v, o);
        if (t == 0) bcast = v;
    }
    __syncthreads();
    float tot = bcast;

    atomicAdd(&alpha[(long)b * TT + t], e / tot);
}

// ---------------- rep = alpha @ hid, then LayerNorm -> path_feature ----------------
__global__ void rep_ln_kernel(const float* __restrict__ hid,
                              const float* __restrict__ alpha,
                              const float* __restrict__ gamma,
                              const float* __restrict__ beta,
                              float* __restrict__ out)
{
    int b = blockIdx.x;
    int tid = threadIdx.x;        // 512
    __shared__ float a_s[TT];
    __shared__ float r_s[DH];
    __shared__ float red[32];
    a_s[tid] = alpha[(long)b * TT + tid];
    __syncthreads();
    if (tid < DH) {
        const float* hb = hid + (long)b * TT * DH;
        float v0 = 0.f, v1 = 0.f, v2 = 0.f, v3 = 0.f;
        #pragma unroll 1
        for (int t = 0; t < TT; t += 4) {
            v0 = fmaf(a_s[t + 0], hb[(long)(t + 0) * DH + tid], v0);
            v1 = fmaf(a_s[t + 1], hb[(long)(t + 1) * DH + tid], v1);
            v2 = fmaf(a_s[t + 2], hb[(long)(t + 2) * DH + tid], v2);
            v3 = fmaf(a_s[t + 3], hb[(long)(t + 3) * DH + tid], v3);
        }
        r_s[tid] = (v0 + v1) + (v2 + v3);
    }
    __syncthreads();
    float p  = (tid < DH) ? r_s[tid] : 0.f;
    float p2 = p * p;
    #pragma unroll
    for (int o = 16; o > 0; o >>= 1) {
        p  += __shfl_xor_sync(0xffffffffu, p,  o);
        p2 += __shfl_xor_sync(0xffffffffu, p2, o);
    }
    if ((tid & 31) == 0) { red[tid >> 5] = p; red[16 + (tid >> 5)] = p2; }
    __syncthreads();
    float mean = 0.f, m2 = 0.f;
    #pragma unroll
    for (int w = 0; w < 16; w++) { mean += red[w]; m2 += red[16 + w]; }
    mean /= (float)DH; m2 /= (float)DH;
    float var = m2 - mean * mean;
    if (tid < DH)
        out[(long)b * DH + tid] =
            (r_s[tid] - mean) * rsqrtf(var + EPS) * gamma[tid] + beta[tid];
}

// ---------------- zero-fill ----------------
__global__ void zero_kernel(float* __restrict__ p, long n)
{
    long i = (long)blockIdx.x * blockDim.x + threadIdx.x;
    if (i < n) p[i] = 0.f;
}

// ---------------- host launcher ----------------
extern "C" void kernel_launch(void* const* d_in, const int* in_sizes, int n_in,
                              void* d_out, int out_size)
{
    const float* nodes   = (const float*)d_in[0];
    const float* ctx     = (const float*)d_in[1];
    const int*   trip    = (const int*)  d_in[2];
    // d_in[3] = node_number (compile-time constant NN = 256)
    const float* W_mean  = (const float*)d_in[4];
    const float* b_mean  = (const float*)d_in[5];
    const float* W_ih_f  = (const float*)d_in[6];
    const float* b_ih_f  = (const float*)d_in[7];
    const float* b_hh_f  = (const float*)d_in[8];
    const float* W_ih_b  = (const float*)d_in[9];
    const float* b_ih_b  = (const float*)d_in[10];
    const float* b_hh_b  = (const float*)d_in[11];
    const float* W_out   = (const float*)d_in[12];
    const float* b_out   = (const float*)d_in[13];
    const float* W_node  = (const float*)d_in[14];
    const float* b_node  = (const float*)d_in[15];
    const float* gamma   = (const float*)d_in[16];
    const float* beta    = (const float*)d_in[17];
    float* out = (float*)d_out;

    float *p_trimean, *p_x, *p_big, *p_hidden, *p_hid, *p_alpha, *p_Wih, *p_bih, *p_zb;
    cudaGetSymbolAddress((void**)&p_trimean, g_trimean);
    cudaGetSymbolAddress((void**)&p_x,       g_x);
    cudaGetSymbolAddress((void**)&p_big,     g_big);
    cudaGetSymbolAddress((void**)&p_hidden,  g_hidden);
    cudaGetSymbolAddress((void**)&p_hid,     g_hid);
    cudaGetSymbolAddress((void**)&p_alpha,   g_alpha);
    cudaGetSymbolAddress((void**)&p_Wih,     g_Wih);
    cudaGetSymbolAddress((void**)&p_bih,     g_bih);
    cudaGetSymbolAddress((void**)&p_zb,      g_zero_bias);

    float* p_gi     = p_big;   // [M_BT, 1800]  GRU phase
    float* p_scores = p_big;   // [B, LQ, TT]   attention phase (disjoint lifetime)

    // 0) concat GRU weights/biases into scratch
    cudaMemcpyAsync(p_Wih,                W_ih_f, (size_t)3 * DH * DH * 4, cudaMemcpyDeviceToDevice);
    cudaMemcpyAsync(p_Wih + 3 * DH * DH,  W_ih_b, (size_t)3 * DH * DH * 4, cudaMemcpyDeviceToDevice);
    cudaMemcpyAsync(p_bih,                b_ih_f, (size_t)3 * DH * 4,      cudaMemcpyDeviceToDevice);
    cudaMemcpyAsync(p_bih + 3 * DH,       b_ih_b, (size_t)3 * DH * 4,      cudaMemcpyDeviceToDevice);

    // 1) tri_mean gather
    {
        long total = (long)M_BT * DN;
        gather_mean_kernel<<<(unsigned)((total + 255) / 256), 256>>>(nodes, trip, p_trimean);
    }
    // 2) x = tri_mean @ W_mean^T + b_mean      [65536,300] K=100
    {
        dim3 g(M_BT / 128, (DH + 127) / 128, 1);
        gemm128_kernel<false><<<g, 256>>>(p_trimean, W_mean, b_mean, p_x,
                                          M_BT, DH, DN, 0, 0, 0);
    }
    // 3) both GRU directions in one GEMM: gi = x @ Wih^T + bih   [65536,1800] K=300
    {
        dim3 g(M_BT / 128, (6 * DH + 127) / 128, 1);
        gemm128_kernel<false><<<g, 256>>>(p_x, p_Wih, p_bih, p_gi,
                                          M_BT, 6 * DH, DH, 0, 0, 0);
    }
    // 4) combined gate activation -> hidden [65536,600]
    {
        long total = (long)M_BT * 2 * DH;
        gru_act2_kernel<<<(unsigned)((total + 255) / 256), 256>>>(p_gi, b_hh_f, b_hh_b, p_hidden);
    }
    // 5) hid_ = tanh(hidden @ W_out^T + b_out)  [65536,300] K=600
    {
        dim3 g(M_BT / 128, (DH + 127) / 128, 1);
        gemm128_kernel<true><<<g, 256>>>(p_hidden, W_out, b_out, p_hid,
                                         M_BT, DH, 2 * DH, 0, 0, 0);
    }
    // 6) scores[b] = ctx[b] @ hid_[b]^T   (batched: M=256, N=512, K=300)
    {
        dim3 g(LQ / 128, TT / 128, BB);
        gemm128_kernel<false><<<g, 256>>>(ctx, p_hid, p_zb, p_scores,
                                          LQ, TT, DH,
                                          (long)LQ * DH, (long)TT * DH,
                                          (long)LQ * TT);
    }
    // 7) alpha = sum_l softmax_t(scores)
    {
        long an = (long)BB * TT;
        zero_kernel<<<(unsigned)((an + 255) / 256), 256>>>(p_alpha, an);
        dim3 g(LQ, BB);
        softmax_row_kernel<<<g, TT>>>(p_scores, p_alpha);
    }
    // 8) rep + LayerNorm -> path_feature (out offset 0)
    rep_ln_kernel<<<BB, TT>>>(p_hid, p_alpha, gamma, beta, out);
    // 9) node_feature = nodes @ W_node^T + b_node -> out offset B*DH
    {
        dim3 g(M_BN / 128, (DH + 127) / 128, 1);
        gemm128_kernel<false><<<g, 256>>>(nodes, W_node, b_node,
                                          out + (long)BB * DH,
                                          M_BN, DH, DN, 0, 0, 0);
    }
    // 10) node_mask zeros, if the output buffer includes it
    {
        long mask_off = (long)BB * DH + (long)M_BN * DH;   // 9,868,800
        long mask_n   = (long)BB * NN;                     // 32,768
        if ((long)out_size >= mask_off + mask_n) {
            zero_kernel<<<(unsigned)((mask_n + 255) / 256), 256>>>(out + mask_off, mask_n);
        }
    }
}

// round 8
// speedup vs baseline: 3.2481x; 1.7356x over previous
#include <cuda_runtime.h>
#include <math.h>
#include <stdint.h>

// ---------------- problem constants ----------------
#define BB   128      // batch
#define TT   512      // triples per dialogue
#define LQ   256      // query length
#define NN   256      // nodes per dialogue
#define DN   100      // node dim
#define DH   300      // hidden dim
#define EPS  1e-5f

#define M_BT (BB*TT)          // 65536
#define M_BN (BB*NN)          // 32768

// ---------------- device scratch (static globals; no allocation) ----------------
__device__ float g_trimean[(long)M_BT * DN];          //  26 MB
__device__ float g_x      [(long)M_BT * DH];          //  79 MB
__device__ float g_big    [(long)M_BT * 6 * DH];      // 472 MB (gi [M,1800]; later scores [B,LQ,TT])
__device__ float g_hidden [(long)M_BT * 2 * DH];      // 157 MB
__device__ float g_hid    [(long)M_BT * DH];          //  79 MB
__device__ float g_alpha  [(long)BB * TT];
__device__ float g_Wih    [2 * 3 * DH * DH];          // concat W_ih_f ; W_ih_b  [1800,300]
__device__ float g_bih    [2 * 3 * DH];               // concat b_ih_f ; b_ih_b  [1800]
__device__ float g_zero_bias[2048];                   // zero-initialized

// =======================================================================
// tf32 mma.sync GEMM:  C[M,N] = A[M,K] * B[N,K]^T + bias  (optional tanh)
// CTA tile 128x128, BK=16, 256 threads (8 warps, 2x4), warp tile 64x32.
// mma.sync.aligned.m16n8k8.row.col.f32.tf32.tf32.f32 (plain sm_80+ PTX —
// works on base sm_103 target; tcgen05 does NOT).
// M % 128 == 0 (all callers); N, K arbitrary (K % 4 == 0 for float4 loads).
// =======================================================================

__device__ __forceinline__ float to_tf32(float x) {
    float y;
    asm("cvt.rna.tf32.f32 %0, %1;" : "=f"(y) : "f"(x));
    return y;
}

#define SM_STRIDE 20   // floats per smem row: conflict-free for frag pattern

template<bool TANH>
__global__ void __launch_bounds__(256)
mma_gemm_kernel(const float* __restrict__ A, const float* __restrict__ Bm,
                const float* __restrict__ bias, float* __restrict__ C,
                int M, int N, int K,
                long strideA, long strideB, long strideC)
{
    __shared__ float As[128][SM_STRIDE];
    __shared__ float Bs[128][SM_STRIDE];

    const int batch = blockIdx.z;
    A  += (long)batch * strideA;
    Bm += (long)batch * strideB;
    C  += (long)batch * strideC;

    const int tid   = threadIdx.x;           // 0..255
    const int wid   = tid >> 5;              // 0..7
    const int lane  = tid & 31;
    const int warpM = wid >> 2;              // 0..1  -> 64-row slab
    const int warpN = wid & 3;               // 0..3  -> 32-col slab
    const int g     = lane >> 2;             // groupID 0..7
    const int t4    = lane & 3;              // threadID_in_group

    const int rowBase = blockIdx.x * 128;
    const int colBase = blockIdx.y * 128;

    float c[4][4][4];
    #pragma unroll
    for (int mt = 0; mt < 4; mt++)
        #pragma unroll
        for (int nt = 0; nt < 4; nt++)
            #pragma unroll
            for (int q = 0; q < 4; q++) c[mt][nt][q] = 0.f;

    const int fr = tid >> 2;       // 0..63? no: 256/4 = 64.. need 128 rows: 2 iters
    const int fq = tid & 3;        // float4 slot within 16-float row chunk

    for (int k0 = 0; k0 < K; k0 += 16) {
        // ---- fill As/Bs: [r][k] k-major rows, tf32-converted ----
        #pragma unroll
        for (int it = 0; it < 2; it++) {
            int r  = fr + it * 64;            // 0..127
            int gk = k0 + fq * 4;
            // A
            float4 va = make_float4(0.f, 0.f, 0.f, 0.f);
            if (gk + 3 < K) {
                va = *reinterpret_cast<const float4*>(&A[(long)(rowBase + r) * K + gk]);
            } else if (gk < K) {
                va.x = A[(long)(rowBase + r) * K + gk];
                if (gk + 1 < K) va.y = A[(long)(rowBase + r) * K + gk + 1];
                if (gk + 2 < K) va.z = A[(long)(rowBase + r) * K + gk + 2];
            }
            As[r][fq * 4 + 0] = to_tf32(va.x);
            As[r][fq * 4 + 1] = to_tf32(va.y);
            As[r][fq * 4 + 2] = to_tf32(va.z);
            As[r][fq * 4 + 3] = to_tf32(va.w);
            // B
            int gn = colBase + r;
            float4 vb = make_float4(0.f, 0.f, 0.f, 0.f);
            if (gn < N) {
                if (gk + 3 < K) {
                    vb = *reinterpret_cast<const float4*>(&Bm[(long)gn * K + gk]);
                } else if (gk < K) {
                    vb.x = Bm[(long)gn * K + gk];
                    if (gk + 1 < K) vb.y = Bm[(long)gn * K + gk + 1];
                    if (gk + 2 < K) vb.z = Bm[(long)gn * K + gk + 2];
                }
            }
            Bs[r][fq * 4 + 0] = to_tf32(vb.x);
            Bs[r][fq * 4 + 1] = to_tf32(vb.y);
            Bs[r][fq * 4 + 2] = to_tf32(vb.z);
            Bs[r][fq * 4 + 3] = to_tf32(vb.w);
        }
        __syncthreads();

        #pragma unroll
        for (int kk = 0; kk < 16; kk += 8) {
            uint32_t ar[4][4], br[4][2];
            #pragma unroll
            for (int mt = 0; mt < 4; mt++) {
                int r0 = warpM * 64 + mt * 16 + g;
                ar[mt][0] = __float_as_uint(As[r0    ][kk + t4    ]);
                ar[mt][1] = __float_as_uint(As[r0 + 8][kk + t4    ]);
                ar[mt][2] = __float_as_uint(As[r0    ][kk + t4 + 4]);
                ar[mt][3] = __float_as_uint(As[r0 + 8][kk + t4 + 4]);
            }
            #pragma unroll
            for (int nt = 0; nt < 4; nt++) {
                int n0 = warpN * 32 + nt * 8 + g;
                br[nt][0] = __float_as_uint(Bs[n0][kk + t4    ]);
                br[nt][1] = __float_as_uint(Bs[n0][kk + t4 + 4]);
            }
            #pragma unroll
            for (int mt = 0; mt < 4; mt++)
                #pragma unroll
                for (int nt = 0; nt < 4; nt++) {
                    asm volatile(
                        "mma.sync.aligned.m16n8k8.row.col.f32.tf32.tf32.f32 "
                        "{%0,%1,%2,%3}, {%4,%5,%6,%7}, {%8,%9}, {%0,%1,%2,%3};"
                        : "+f"(c[mt][nt][0]), "+f"(c[mt][nt][1]),
                          "+f"(c[mt][nt][2]), "+f"(c[mt][nt][3])
                        : "r"(ar[mt][0]), "r"(ar[mt][1]), "r"(ar[mt][2]), "r"(ar[mt][3]),
                          "r"(br[nt][0]), "r"(br[nt][1]));
                }
        }
        __syncthreads();
    }

    // ---- epilogue: c layout -> C[row][col], bias (+tanh), float2 stores ----
    #pragma unroll
    for (int mt = 0; mt < 4; mt++) {
        int r0 = rowBase + warpM * 64 + mt * 16 + g;
        #pragma unroll
        for (int nt = 0; nt < 4; nt++) {
            int col0 = colBase + warpN * 32 + nt * 8 + 2 * t4;
            if (col0 + 1 < N) {
                float b0 = bias[col0], b1 = bias[col0 + 1];
                float2 v0 = make_float2(c[mt][nt][0] + b0, c[mt][nt][1] + b1);
                float2 v1 = make_float2(c[mt][nt][2] + b0, c[mt][nt][3] + b1);
                if (TANH) {
                    v0.x = tanhf(v0.x); v0.y = tanhf(v0.y);
                    v1.x = tanhf(v1.x); v1.y = tanhf(v1.y);
                }
                *reinterpret_cast<float2*>(&C[(long)r0 * N + col0]) = v0;
                *reinterpret_cast<float2*>(&C[(long)(r0 + 8) * N + col0]) = v1;
            } else if (col0 < N) {
                float b0 = bias[col0];
                float v0 = c[mt][nt][0] + b0;
                float v1 = c[mt][nt][2] + b0;
                if (TANH) { v0 = tanhf(v0); v1 = tanhf(v1); }
                C[(long)r0 * N + col0] = v0;
                C[(long)(r0 + 8) * N + col0] = v1;
            }
        }
    }
}

// ---------------- gather + mean of head/tail node vectors (float4) ----------------
__global__ void gather_mean_kernel(const float4* __restrict__ nodes,
                                   const int* __restrict__ trip,
                                   float4* __restrict__ out)
{
    long idx = (long)blockIdx.x * blockDim.x + threadIdx.x;    // over M_BT*25
    long total = (long)M_BT * (DN / 4);
    if (idx >= total) return;
    int d4 = (int)(idx % (DN / 4));
    long bt = idx / (DN / 4);
    int b = (int)(bt / TT);
    int t = (int)(bt % TT);
    int h  = trip[((long)b * TT + t) * 3 + 0];
    int tl = trip[((long)b * TT + t) * 3 + 2];
    float4 vh = nodes[((long)b * NN + h)  * (DN / 4) + d4];
    float4 vt = nodes[((long)b * NN + tl) * (DN / 4) + d4];
    out[idx] = make_float4(0.5f * (vh.x + vt.x), 0.5f * (vh.y + vt.y),
                           0.5f * (vh.z + vt.z), 0.5f * (vh.w + vt.w));
}

// ---------------- combined GRU gate activation, float4 ----------------
__device__ __forceinline__ float4 sig4(float4 a) {
    return make_float4(1.f / (1.f + expf(-a.x)), 1.f / (1.f + expf(-a.y)),
                       1.f / (1.f + expf(-a.z)), 1.f / (1.f + expf(-a.w)));
}
__global__ void gru_act2_kernel(const float4* __restrict__ gi,
                                const float4* __restrict__ b_hh_f,
                                const float4* __restrict__ b_hh_b,
                                float4* __restrict__ hidden)
{
    long idx = (long)blockIdx.x * blockDim.x + threadIdx.x;   // over M_BT*150
    long total = (long)M_BT * (2 * DH / 4);
    if (idx >= total) return;
    long i = idx / 150;
    int  c4 = (int)(idx % 150);
    int dir = c4 / 75;
    int j4  = c4 % 75;
    const float4* gir = gi + i * 450 + (long)dir * 225;
    const float4* bh  = dir ? b_hh_b : b_hh_f;
    float4 R = gir[j4],      br = bh[j4];
    float4 Z = gir[75 + j4], bz = bh[75 + j4];
    float4 Nv = gir[150 + j4], bn = bh[150 + j4];
    float4 rr = sig4(make_float4(R.x + br.x, R.y + br.y, R.z + br.z, R.w + br.w));
    float4 zz = sig4(make_float4(Z.x + bz.x, Z.y + bz.y, Z.z + bz.z, Z.w + bz.w));
    float4 nn = make_float4(tanhf(Nv.x + rr.x * bn.x), tanhf(Nv.y + rr.y * bn.y),
                            tanhf(Nv.z + rr.z * bn.z), tanhf(Nv.w + rr.w * bn.w));
    hidden[i * 150 + c4] = make_float4((1.f - zz.x) * nn.x, (1.f - zz.y) * nn.y,
                                       (1.f - zz.z) * nn.z, (1.f - zz.w) * nn.w);
}

// ---------------- per-row softmax + atomic alpha accumulation ----------------
__global__ void softmax_row_kernel(const float* __restrict__ S,
                                   float* __restrict__ alpha)
{
    int l = blockIdx.x, b = blockIdx.y;
    int t = threadIdx.x;                 // 0..511
    __shared__ float red[16];
    __shared__ float bcast;
    const float* row = S + ((long)b * LQ + l) * TT;
    float s = row[t];

    float m = s;
    #pragma unroll
    for (int o = 16; o > 0; o >>= 1) m = fmaxf(m, __shfl_xor_sync(0xffffffffu, m, o));
    if ((t & 31) == 0) red[t >> 5] = m;
    __syncthreads();
    if (t < 16) {
        float v = red[t];
        #pragma unroll
        for (int o = 8; o > 0; o >>= 1) v = fmaxf(v, __shfl_xor_sync(0xffffu, v, o));
        if (t == 0) bcast = v;
    }
    __syncthreads();
    float bm = bcast;

    float e = expf(s - bm);
    float sm = e;
    #pragma unroll
    for (int o = 16; o > 0; o >>= 1) sm += __shfl_xor_sync(0xffffffffu, sm, o);
    if ((t & 31) == 0) red[t >> 5] = sm;
    __syncthreads();
    if (t < 16) {
        float v = red[t];
        #pragma unroll
        for (int o = 8; o > 0; o >>= 1) v += __shfl_xor_sync(0xffffu, v, o);
        if (t == 0) bcast = v;
    }
    __syncthreads();
    float tot = bcast;

    atomicAdd(&alpha[(long)b * TT + t], e / tot);
}

// ---------------- rep = alpha @ hid, then LayerNorm -> path_feature ----------------
__global__ void rep_ln_kernel(const float* __restrict__ hid,
                              const float* __restrict__ alpha,
                              const float* __restrict__ gamma,
                              const float* __restrict__ beta,
                              float* __restrict__ out)
{
    int b = blockIdx.x;
    int tid = threadIdx.x;        // 512
    __shared__ float a_s[TT];
    __shared__ float r_s[DH];
    __shared__ float red[32];
    a_s[tid] = alpha[(long)b * TT + tid];
    __syncthreads();
    if (tid < DH) {
        const float* hb = hid + (long)b * TT * DH;
        float v0 = 0.f, v1 = 0.f, v2 = 0.f, v3 = 0.f;
        #pragma unroll 1
        for (int t = 0; t < TT; t += 4) {
            v0 = fmaf(a_s[t + 0], hb[(long)(t + 0) * DH + tid], v0);
            v1 = fmaf(a_s[t + 1], hb[(long)(t + 1) * DH + tid], v1);
            v2 = fmaf(a_s[t + 2], hb[(long)(t + 2) * DH + tid], v2);
            v3 = fmaf(a_s[t + 3], hb[(long)(t + 3) * DH + tid], v3);
        }
        r_s[tid] = (v0 + v1) + (v2 + v3);
    }
    __syncthreads();
    float p  = (tid < DH) ? r_s[tid] : 0.f;
    float p2 = p * p;
    #pragma unroll
    for (int o = 16; o > 0; o >>= 1) {
        p  += __shfl_xor_sync(0xffffffffu, p,  o);
        p2 += __shfl_xor_sync(0xffffffffu, p2, o);
    }
    if ((tid & 31) == 0) { red[tid >> 5] = p; red[16 + (tid >> 5)] = p2; }
    __syncthreads();
    float mean = 0.f, m2 = 0.f;
    #pragma unroll
    for (int w = 0; w < 16; w++) { mean += red[w]; m2 += red[16 + w]; }
    mean /= (float)DH; m2 /= (float)DH;
    float var = m2 - mean * mean;
    if (tid < DH)
        out[(long)b * DH + tid] =
            (r_s[tid] - mean) * rsqrtf(var + EPS) * gamma[tid] + beta[tid];
}

// ---------------- zero-fill ----------------
__global__ void zero_kernel(float* __restrict__ p, long n)
{
    long i = (long)blockIdx.x * blockDim.x + threadIdx.x;
    if (i < n) p[i] = 0.f;
}

// ---------------- host launcher ----------------
extern "C" void kernel_launch(void* const* d_in, const int* in_sizes, int n_in,
                              void* d_out, int out_size)
{
    const float* nodes   = (const float*)d_in[0];
    const float* ctx     = (const float*)d_in[1];
    const int*   trip    = (const int*)  d_in[2];
    // d_in[3] = node_number (compile-time constant NN = 256)
    const float* W_mean  = (const float*)d_in[4];
    const float* b_mean  = (const float*)d_in[5];
    const float* W_ih_f  = (const float*)d_in[6];
    const float* b_ih_f  = (const float*)d_in[7];
    const float* b_hh_f  = (const float*)d_in[8];
    const float* W_ih_b  = (const float*)d_in[9];
    const float* b_ih_b  = (const float*)d_in[10];
    const float* b_hh_b  = (const float*)d_in[11];
    const float* W_out   = (const float*)d_in[12];
    const float* b_out   = (const float*)d_in[13];
    const float* W_node  = (const float*)d_in[14];
    const float* b_node  = (const float*)d_in[15];
    const float* gamma   = (const float*)d_in[16];
    const float* beta    = (const float*)d_in[17];
    float* out = (float*)d_out;

    float *p_trimean, *p_x, *p_big, *p_hidden, *p_hid, *p_alpha, *p_Wih, *p_bih, *p_zb;
    cudaGetSymbolAddress((void**)&p_trimean, g_trimean);
    cudaGetSymbolAddress((void**)&p_x,       g_x);
    cudaGetSymbolAddress((void**)&p_big,     g_big);
    cudaGetSymbolAddress((void**)&p_hidden,  g_hidden);
    cudaGetSymbolAddress((void**)&p_hid,     g_hid);
    cudaGetSymbolAddress((void**)&p_alpha,   g_alpha);
    cudaGetSymbolAddress((void**)&p_Wih,     g_Wih);
    cudaGetSymbolAddress((void**)&p_bih,     g_bih);
    cudaGetSymbolAddress((void**)&p_zb,      g_zero_bias);

    float* p_gi     = p_big;   // [M_BT, 1800]  GRU phase
    float* p_scores = p_big;   // [B, LQ, TT]   attention phase (disjoint lifetime)

    // 0) concat GRU weights/biases into scratch
    cudaMemcpyAsync(p_Wih,                W_ih_f, (size_t)3 * DH * DH * 4, cudaMemcpyDeviceToDevice);
    cudaMemcpyAsync(p_Wih + 3 * DH * DH,  W_ih_b, (size_t)3 * DH * DH * 4, cudaMemcpyDeviceToDevice);
    cudaMemcpyAsync(p_bih,                b_ih_f, (size_t)3 * DH * 4,      cudaMemcpyDeviceToDevice);
    cudaMemcpyAsync(p_bih + 3 * DH,       b_ih_b, (size_t)3 * DH * 4,      cudaMemcpyDeviceToDevice);

    // 1) tri_mean gather
    {
        long total = (long)M_BT * (DN / 4);
        gather_mean_kernel<<<(unsigned)((total + 255) / 256), 256>>>(
            (const float4*)nodes, trip, (float4*)p_trimean);
    }
    // 2) x = tri_mean @ W_mean^T + b_mean      [65536,300] K=100
    {
        dim3 g(M_BT / 128, (DH + 127) / 128, 1);
        mma_gemm_kernel<false><<<g, 256>>>(p_trimean, W_mean, b_mean, p_x,
                                           M_BT, DH, DN, 0, 0, 0);
    }
    // 3) both GRU directions in one GEMM: gi = x @ Wih^T + bih   [65536,1800] K=300
    {
        dim3 g(M_BT / 128, (6 * DH + 127) / 128, 1);
        mma_gemm_kernel<false><<<g, 256>>>(p_x, p_Wih, p_bih, p_gi,
                                           M_BT, 6 * DH, DH, 0, 0, 0);
    }
    // 4) combined gate activation -> hidden [65536,600]
    {
        long total = (long)M_BT * (2 * DH / 4);
        gru_act2_kernel<<<(unsigned)((total + 255) / 256), 256>>>(
            (const float4*)p_gi, (const float4*)b_hh_f, (const float4*)b_hh_b,
            (float4*)p_hidden);
    }
    // 5) hid_ = tanh(hidden @ W_out^T + b_out)  [65536,300] K=600
    {
        dim3 g(M_BT / 128, (DH + 127) / 128, 1);
        mma_gemm_kernel<true><<<g, 256>>>(p_hidden, W_out, b_out, p_hid,
                                          M_BT, DH, 2 * DH, 0, 0, 0);
    }
    // 6) scores[b] = ctx[b] @ hid_[b]^T   (batched: M=256, N=512, K=300)
    {
        dim3 g(LQ / 128, TT / 128, BB);
        mma_gemm_kernel<false><<<g, 256>>>(ctx, p_hid, p_zb, p_scores,
                                           LQ, TT, DH,
                                           (long)LQ * DH, (long)TT * DH,
                                           (long)LQ * TT);
    }
    // 7) alpha = sum_l softmax_t(scores)
    {
        long an = (long)BB * TT;
        zero_kernel<<<(unsigned)((an + 255) / 256), 256>>>(p_alpha, an);
        dim3 g(LQ, BB);
        softmax_row_kernel<<<g, TT>>>(p_scores, p_alpha);
    }
    // 8) rep + LayerNorm -> path_feature (out offset 0)
    rep_ln_kernel<<<BB, TT>>>(p_hid, p_alpha, gamma, beta, out);
    // 9) node_feature = nodes @ W_node^T + b_node -> out offset B*DH
    {
        dim3 g(M_BN / 128, (DH + 127) / 128, 1);
        mma_gemm_kernel<false><<<g, 256>>>(nodes, W_node, b_node,
                                           out + (long)BB * DH,
                                           M_BN, DH, DN, 0, 0, 0);
    }
    // 10) node_mask zeros, if the output buffer includes it
    {
        long mask_off = (long)BB * DH + (long)M_BN * DH;   // 9,868,800
        long mask_n   = (long)BB * NN;                     // 32,768
        if ((long)out_size >= mask_off + mask_n) {
            zero_kernel<<<(unsigned)((mask_n + 255) / 256), 256>>>(out + mask_off, mask_n);
        }
    }
}

// round 9
// speedup vs baseline: 6.0186x; 1.8529x over previous
#include <cuda_runtime.h>
#include <math.h>
#include <stdint.h>

// ---------------- problem constants ----------------
#define BB   128      // batch
#define TT   512      // triples per dialogue
#define LQ   256      // query length
#define NN   256      // nodes per dialogue
#define DN   100      // node dim
#define DH   300      // hidden dim
#define EPS  1e-5f

#define M_BT (BB*TT)          // 65536
#define M_BN (BB*NN)          // 32768

// ---------------- device scratch (static globals; no allocation) ----------------
__device__ float g_trimean[(long)M_BT * DN];          //  26 MB
__device__ float g_x      [(long)M_BT * DH];          //  79 MB
__device__ float g_big    [(long)M_BT * 6 * DH];      // 472 MB (gi [M,1800]; later scores [B,LQ,TT])
__device__ float g_hidden [(long)M_BT * 2 * DH];      // 157 MB
__device__ float g_hid    [(long)M_BT * DH];          //  79 MB
__device__ float g_alpha  [(long)BB * TT];
__device__ float g_Wih    [2 * 3 * DH * DH];          // concat W_ih_f ; W_ih_b  [1800,300]
__device__ float g_bih    [2 * 3 * DH];               // concat b_ih_f ; b_ih_b  [1800]
__device__ float g_zero_bias[2048];                   // zero-initialized

// =======================================================================
// tf32 mma.sync GEMM, cp.async double-buffered:
//   C[M,N] = A[M,K] * B[N,K]^T + bias   (optional tanh)
// CTA tile 128x128, BK=16, 256 threads (8 warps, 2x4), warp tile 64x32.
// grid.x = N tiles (fast — shares A slab via L2), grid.y = M tiles.
// M % 128 == 0; K % 4 == 0; N arbitrary.
// =======================================================================

__device__ __forceinline__ uint32_t to_tf32_bits(float x) {
    float y;
    asm("cvt.rna.tf32.f32 %0, %1;" : "=f"(y) : "f"(x));
    return __float_as_uint(y);
}

#define SM_STRIDE 20   // floats per smem row: conflict-free for frag pattern

template<bool TANH>
__global__ void __launch_bounds__(256)
mma_gemm_kernel(const float* __restrict__ A, const float* __restrict__ Bm,
                const float* __restrict__ bias, float* __restrict__ C,
                int M, int N, int K,
                long strideA, long strideB, long strideC)
{
    __shared__ float As[2][128][SM_STRIDE];
    __shared__ float Bs[2][128][SM_STRIDE];

    const int batch = blockIdx.z;
    A  += (long)batch * strideA;
    Bm += (long)batch * strideB;
    C  += (long)batch * strideC;

    const int tid   = threadIdx.x;           // 0..255
    const int wid   = tid >> 5;              // 0..7
    const int lane  = tid & 31;
    const int warpM = wid >> 2;              // 0..1  -> 64-row slab
    const int warpN = wid & 3;               // 0..3  -> 32-col slab
    const int g     = lane >> 2;             // groupID 0..7
    const int t4    = lane & 3;              // threadID_in_group

    const int rowBase = blockIdx.y * 128;    // M tile (grid.y)
    const int colBase = blockIdx.x * 128;    // N tile (grid.x, fast-varying)

    const int fr = tid >> 2;                 // 0..63
    const int fq = tid & 3;                  // 16B chunk within row

    float c[4][4][4];
    #pragma unroll
    for (int mt = 0; mt < 4; mt++)
        #pragma unroll
        for (int nt = 0; nt < 4; nt++)
            #pragma unroll
            for (int q = 0; q < 4; q++) c[mt][nt][q] = 0.f;

    const int nStages = (K + 15) / 16;

    // stage loader: issue 4 cp.async (2 A rows, 2 B rows) into buffer `buf`
    auto load_stage = [&](int s, int buf) {
        const int k0 = s * 16;
        const int gk = k0 + fq * 4;
        #pragma unroll
        for (int it = 0; it < 2; it++) {
            int r = fr + it * 64;
            // A
            {
                uint32_t dst = (uint32_t)__cvta_generic_to_shared(&As[buf][r][fq * 4]);
                const float* src = (gk < K) ? &A[(long)(rowBase + r) * K + gk] : A;
                int sz = (gk < K) ? 16 : 0;
                asm volatile("cp.async.ca.shared.global [%0], [%1], 16, %2;"
                             :: "r"(dst), "l"(src), "r"(sz));
            }
            // B
            {
                int gn = colBase + r;
                bool ok = (gn < N) && (gk < K);
                uint32_t dst = (uint32_t)__cvta_generic_to_shared(&Bs[buf][r][fq * 4]);
                const float* src = ok ? &Bm[(long)gn * K + gk] : Bm;
                int sz = ok ? 16 : 0;
                asm volatile("cp.async.ca.shared.global [%0], [%1], 16, %2;"
                             :: "r"(dst), "l"(src), "r"(sz));
            }
        }
        asm volatile("cp.async.commit_group;");
    };

    load_stage(0, 0);

    for (int s = 0; s < nStages; s++) {
        const int buf = s & 1;
        if (s + 1 < nStages) {
            load_stage(s + 1, (s + 1) & 1);
            asm volatile("cp.async.wait_group 1;");
        } else {
            asm volatile("cp.async.wait_group 0;");
        }
        __syncthreads();

        #pragma unroll
        for (int kk = 0; kk < 16; kk += 8) {
            uint32_t ar[4][4], br[4][2];
            #pragma unroll
            for (int mt = 0; mt < 4; mt++) {
                int r0 = warpM * 64 + mt * 16 + g;
                ar[mt][0] = to_tf32_bits(As[buf][r0    ][kk + t4    ]);
                ar[mt][1] = to_tf32_bits(As[buf][r0 + 8][kk + t4    ]);
                ar[mt][2] = to_tf32_bits(As[buf][r0    ][kk + t4 + 4]);
                ar[mt][3] = to_tf32_bits(As[buf][r0 + 8][kk + t4 + 4]);
            }
            #pragma unroll
            for (int nt = 0; nt < 4; nt++) {
                int n0 = warpN * 32 + nt * 8 + g;
                br[nt][0] = to_tf32_bits(Bs[buf][n0][kk + t4    ]);
                br[nt][1] = to_tf32_bits(Bs[buf][n0][kk + t4 + 4]);
            }
            #pragma unroll
            for (int mt = 0; mt < 4; mt++)
                #pragma unroll
                for (int nt = 0; nt < 4; nt++) {
                    asm volatile(
                        "mma.sync.aligned.m16n8k8.row.col.f32.tf32.tf32.f32 "
                        "{%0,%1,%2,%3}, {%4,%5,%6,%7}, {%8,%9}, {%0,%1,%2,%3};"
                        : "+f"(c[mt][nt][0]), "+f"(c[mt][nt][1]),
                          "+f"(c[mt][nt][2]), "+f"(c[mt][nt][3])
                        : "r"(ar[mt][0]), "r"(ar[mt][1]), "r"(ar[mt][2]), "r"(ar[mt][3]),
                          "r"(br[nt][0]), "r"(br[nt][1]));
                }
        }
        __syncthreads();   // protect buf before it is overwritten two stages later
    }

    // ---- epilogue: bias (+tanh), float2 stores ----
    #pragma unroll
    for (int mt = 0; mt < 4; mt++) {
        int r0 = rowBase + warpM * 64 + mt * 16 + g;
        #pragma unroll
        for (int nt = 0; nt < 4; nt++) {
            int col0 = colBase + warpN * 32 + nt * 8 + 2 * t4;
            if (col0 + 1 < N) {
                float b0 = bias[col0], b1 = bias[col0 + 1];
                float2 v0 = make_float2(c[mt][nt][0] + b0, c[mt][nt][1] + b1);
                float2 v1 = make_float2(c[mt][nt][2] + b0, c[mt][nt][3] + b1);
                if (TANH) {
                    v0.x = tanhf(v0.x); v0.y = tanhf(v0.y);
                    v1.x = tanhf(v1.x); v1.y = tanhf(v1.y);
                }
                *reinterpret_cast<float2*>(&C[(long)r0 * N + col0]) = v0;
                *reinterpret_cast<float2*>(&C[(long)(r0 + 8) * N + col0]) = v1;
            } else if (col0 < N) {
                float b0 = bias[col0];
                float v0 = c[mt][nt][0] + b0;
                float v1 = c[mt][nt][2] + b0;
                if (TANH) { v0 = tanhf(v0); v1 = tanhf(v1); }
                C[(long)r0 * N + col0] = v0;
                C[(long)(r0 + 8) * N + col0] = v1;
            }
        }
    }
}

// ---------------- gather + mean of head/tail node vectors (float4) ----------------
__global__ void gather_mean_kernel(const float4* __restrict__ nodes,
                                   const int* __restrict__ trip,
                                   float4* __restrict__ out)
{
    long idx = (long)blockIdx.x * blockDim.x + threadIdx.x;    // over M_BT*25
    long total = (long)M_BT * (DN / 4);
    if (idx >= total) return;
    int d4 = (int)(idx % (DN / 4));
    long bt = idx / (DN / 4);
    int b = (int)(bt / TT);
    int t = (int)(bt % TT);
    int h  = trip[((long)b * TT + t) * 3 + 0];
    int tl = trip[((long)b * TT + t) * 3 + 2];
    float4 vh = nodes[((long)b * NN + h)  * (DN / 4) + d4];
    float4 vt = nodes[((long)b * NN + tl) * (DN / 4) + d4];
    out[idx] = make_float4(0.5f * (vh.x + vt.x), 0.5f * (vh.y + vt.y),
                           0.5f * (vh.z + vt.z), 0.5f * (vh.w + vt.w));
}

// ---------------- combined GRU gate activation, float4 ----------------
__device__ __forceinline__ float4 sig4(float4 a) {
    return make_float4(1.f / (1.f + expf(-a.x)), 1.f / (1.f + expf(-a.y)),
                       1.f / (1.f + expf(-a.z)), 1.f / (1.f + expf(-a.w)));
}
__global__ void gru_act2_kernel(const float4* __restrict__ gi,
                                const float4* __restrict__ b_hh_f,
                                const float4* __restrict__ b_hh_b,
                                float4* __restrict__ hidden)
{
    long idx = (long)blockIdx.x * blockDim.x + threadIdx.x;   // over M_BT*150
    long total = (long)M_BT * (2 * DH / 4);
    if (idx >= total) return;
    long i = idx / 150;
    int  c4 = (int)(idx % 150);
    int dir = c4 / 75;
    int j4  = c4 % 75;
    const float4* gir = gi + i * 450 + (long)dir * 225;
    const float4* bh  = dir ? b_hh_b : b_hh_f;
    float4 R = gir[j4],      br = bh[j4];
    float4 Z = gir[75 + j4], bz = bh[75 + j4];
    float4 Nv = gir[150 + j4], bn = bh[150 + j4];
    float4 rr = sig4(make_float4(R.x + br.x, R.y + br.y, R.z + br.z, R.w + br.w));
    float4 zz = sig4(make_float4(Z.x + bz.x, Z.y + bz.y, Z.z + bz.z, Z.w + bz.w));
    float4 nn = make_float4(tanhf(Nv.x + rr.x * bn.x), tanhf(Nv.y + rr.y * bn.y),
                            tanhf(Nv.z + rr.z * bn.z), tanhf(Nv.w + rr.w * bn.w));
    hidden[i * 150 + c4] = make_float4((1.f - zz.x) * nn.x, (1.f - zz.y) * nn.y,
                                       (1.f - zz.z) * nn.z, (1.f - zz.w) * nn.w);
}

// ---------------- per-row softmax + atomic alpha accumulation ----------------
__global__ void softmax_row_kernel(const float* __restrict__ S,
                                   float* __restrict__ alpha)
{
    int l = blockIdx.x, b = blockIdx.y;
    int t = threadIdx.x;                 // 0..511
    __shared__ float red[16];
    __shared__ float bcast;
    const float* row = S + ((long)b * LQ + l) * TT;
    float s = row[t];

    float m = s;
    #pragma unroll
    for (int o = 16; o > 0; o >>= 1) m = fmaxf(m, __shfl_xor_sync(0xffffffffu, m, o));
    if ((t & 31) == 0) red[t >> 5] = m;
    __syncthreads();
    if (t < 16) {
        float v = red[t];
        #pragma unroll
        for (int o = 8; o > 0; o >>= 1) v = fmaxf(v, __shfl_xor_sync(0xffffu, v, o));
        if (t == 0) bcast = v;
    }
    __syncthreads();
    float bm = bcast;

    float e = expf(s - bm);
    float sm = e;
    #pragma unroll
    for (int o = 16; o > 0; o >>= 1) sm += __shfl_xor_sync(0xffffffffu, sm, o);
    if ((t & 31) == 0) red[t >> 5] = sm;
    __syncthreads();
    if (t < 16) {
        float v = red[t];
        #pragma unroll
        for (int o = 8; o > 0; o >>= 1) v += __shfl_xor_sync(0xffffu, v, o);
        if (t == 0) bcast = v;
    }
    __syncthreads();
    float tot = bcast;

    atomicAdd(&alpha[(long)b * TT + t], e / tot);
}

// ---------------- rep = alpha @ hid, then LayerNorm -> path_feature ----------------
__global__ void rep_ln_kernel(const float* __restrict__ hid,
                              const float* __restrict__ alpha,
                              const float* __restrict__ gamma,
                              const float* __restrict__ beta,
                              float* __restrict__ out)
{
    int b = blockIdx.x;
    int tid = threadIdx.x;        // 512
    __shared__ float a_s[TT];
    __shared__ float r_s[DH];
    __shared__ float red[32];
    a_s[tid] = alpha[(long)b * TT + tid];
    __syncthreads();
    if (tid < DH) {
        const float* hb = hid + (long)b * TT * DH;
        float v0 = 0.f, v1 = 0.f, v2 = 0.f, v3 = 0.f;
        #pragma unroll 1
        for (int t = 0; t < TT; t += 4) {
            v0 = fmaf(a_s[t + 0], hb[(long)(t + 0) * DH + tid], v0);
            v1 = fmaf(a_s[t + 1], hb[(long)(t + 1) * DH + tid], v1);
            v2 = fmaf(a_s[t + 2], hb[(long)(t + 2) * DH + tid], v2);
            v3 = fmaf(a_s[t + 3], hb[(long)(t + 3) * DH + tid], v3);
        }
        r_s[tid] = (v0 + v1) + (v2 + v3);
    }
    __syncthreads();
    float p  = (tid < DH) ? r_s[tid] : 0.f;
    float p2 = p * p;
    #pragma unroll
    for (int o = 16; o > 0; o >>= 1) {
        p  += __shfl_xor_sync(0xffffffffu, p,  o);
        p2 += __shfl_xor_sync(0xffffffffu, p2, o);
    }
    if ((tid & 31) == 0) { red[tid >> 5] = p; red[16 + (tid >> 5)] = p2; }
    __syncthreads();
    float mean = 0.f, m2 = 0.f;
    #pragma unroll
    for (int w = 0; w < 16; w++) { mean += red[w]; m2 += red[16 + w]; }
    mean /= (float)DH; m2 /= (float)DH;
    float var = m2 - mean * mean;
    if (tid < DH)
        out[(long)b * DH + tid] =
            (r_s[tid] - mean) * rsqrtf(var + EPS) * gamma[tid] + beta[tid];
}

// ---------------- zero-fill ----------------
__global__ void zero_kernel(float* __restrict__ p, long n)
{
    long i = (long)blockIdx.x * blockDim.x + threadIdx.x;
    if (i < n) p[i] = 0.f;
}

// ---------------- host launcher ----------------
extern "C" void kernel_launch(void* const* d_in, const int* in_sizes, int n_in,
                              void* d_out, int out_size)
{
    const float* nodes   = (const float*)d_in[0];
    const float* ctx     = (const float*)d_in[1];
    const int*   trip    = (const int*)  d_in[2];
    // d_in[3] = node_number (compile-time constant NN = 256)
    const float* W_mean  = (const float*)d_in[4];
    const float* b_mean  = (const float*)d_in[5];
    const float* W_ih_f  = (const float*)d_in[6];
    const float* b_ih_f  = (const float*)d_in[7];
    const float* b_hh_f  = (const float*)d_in[8];
    const float* W_ih_b  = (const float*)d_in[9];
    const float* b_ih_b  = (const float*)d_in[10];
    const float* b_hh_b  = (const float*)d_in[11];
    const float* W_out   = (const float*)d_in[12];
    const float* b_out   = (const float*)d_in[13];
    const float* W_node  = (const float*)d_in[14];
    const float* b_node  = (const float*)d_in[15];
    const float* gamma   = (const float*)d_in[16];
    const float* beta    = (const float*)d_in[17];
    float* out = (float*)d_out;

    float *p_trimean, *p_x, *p_big, *p_hidden, *p_hid, *p_alpha, *p_Wih, *p_bih, *p_zb;
    cudaGetSymbolAddress((void**)&p_trimean, g_trimean);
    cudaGetSymbolAddress((void**)&p_x,       g_x);
    cudaGetSymbolAddress((void**)&p_big,     g_big);
    cudaGetSymbolAddress((void**)&p_hidden,  g_hidden);
    cudaGetSymbolAddress((void**)&p_hid,     g_hid);
    cudaGetSymbolAddress((void**)&p_alpha,   g_alpha);
    cudaGetSymbolAddress((void**)&p_Wih,     g_Wih);
    cudaGetSymbolAddress((void**)&p_bih,     g_bih);
    cudaGetSymbolAddress((void**)&p_zb,      g_zero_bias);

    float* p_gi     = p_big;   // [M_BT, 1800]  GRU phase
    float* p_scores = p_big;   // [B, LQ, TT]   attention phase (disjoint lifetime)

    // 0) concat GRU weights/biases into scratch
    cudaMemcpyAsync(p_Wih,                W_ih_f, (size_t)3 * DH * DH * 4, cudaMemcpyDeviceToDevice);
    cudaMemcpyAsync(p_Wih + 3 * DH * DH,  W_ih_b, (size_t)3 * DH * DH * 4, cudaMemcpyDeviceToDevice);
    cudaMemcpyAsync(p_bih,                b_ih_f, (size_t)3 * DH * 4,      cudaMemcpyDeviceToDevice);
    cudaMemcpyAsync(p_bih + 3 * DH,       b_ih_b, (size_t)3 * DH * 4,      cudaMemcpyDeviceToDevice);

    // 1) tri_mean gather
    {
        long total = (long)M_BT * (DN / 4);
        gather_mean_kernel<<<(unsigned)((total + 255) / 256), 256>>>(
            (const float4*)nodes, trip, (float4*)p_trimean);
    }
    // 2) x = tri_mean @ W_mean^T + b_mean      [65536,300] K=100
    {
        dim3 g((DH + 127) / 128, M_BT / 128, 1);
        mma_gemm_kernel<false><<<g, 256>>>(p_trimean, W_mean, b_mean, p_x,
                                           M_BT, DH, DN, 0, 0, 0);
    }
    // 3) both GRU directions in one GEMM: gi = x @ Wih^T + bih   [65536,1800] K=300
    {
        dim3 g((6 * DH + 127) / 128, M_BT / 128, 1);
        mma_gemm_kernel<false><<<g, 256>>>(p_x, p_Wih, p_bih, p_gi,
                                           M_BT, 6 * DH, DH, 0, 0, 0);
    }
    // 4) combined gate activation -> hidden [65536,600]
    {
        long total = (long)M_BT * (2 * DH / 4);
        gru_act2_kernel<<<(unsigned)((total + 255) / 256), 256>>>(
            (const float4*)p_gi, (const float4*)b_hh_f, (const float4*)b_hh_b,
            (float4*)p_hidden);
    }
    // 5) hid_ = tanh(hidden @ W_out^T + b_out)  [65536,300] K=600
    {
        dim3 g((DH + 127) / 128, M_BT / 128, 1);
        mma_gemm_kernel<true><<<g, 256>>>(p_hidden, W_out, b_out, p_hid,
                                          M_BT, DH, 2 * DH, 0, 0, 0);
    }
    // 6) scores[b] = ctx[b] @ hid_[b]^T   (batched: M=256, N=512, K=300)
    {
        dim3 g(TT / 128, LQ / 128, BB);
        mma_gemm_kernel<false><<<g, 256>>>(ctx, p_hid, p_zb, p_scores,
                                           LQ, TT, DH,
                                           (long)LQ * DH, (long)TT * DH,
                                           (long)LQ * TT);
    }
    // 7) alpha = sum_l softmax_t(scores)
    {
        long an = (long)BB * TT;
        zero_kernel<<<(unsigned)((an + 255) / 256), 256>>>(p_alpha, an);
        dim3 g(LQ, BB);
        softmax_row_kernel<<<g, TT>>>(p_scores, p_alpha);
    }
    // 8) rep + LayerNorm -> path_feature (out offset 0)
    rep_ln_kernel<<<BB, TT>>>(p_hid, p_alpha, gamma, beta, out);
    // 9) node_feature = nodes @ W_node^T + b_node -> out offset B*DH
    {
        dim3 g((DH + 127) / 128, M_BN / 128, 1);
        mma_gemm_kernel<false><<<g, 256>>>(nodes, W_node, b_node,
                                           out + (long)BB * DH,
                                           M_BN, DH, DN, 0, 0, 0);
    }
    // 10) node_mask zeros, if the output buffer includes it
    {
        long mask_off = (long)BB * DH + (long)M_BN * DH;   // 9,868,800
        long mask_n   = (long)BB * NN;                     // 32,768
        if ((long)out_size >= mask_off + mask_n) {
            zero_kernel<<<(unsigned)((mask_n + 255) / 256), 256>>>(out + mask_off, mask_n);
        }
    }
}

// round 10
// speedup vs baseline: 6.2124x; 1.0322x over previous
#include <cuda_runtime.h>
#include <math.h>
#include <stdint.h>

// ---------------- problem constants ----------------
#define BB   128      // batch
#define TT   512      // triples per dialogue
#define LQ   256      // query length
#define NN   256      // nodes per dialogue
#define DN   100      // node dim
#define DH   300      // hidden dim
#define EPS  1e-5f

#define M_BT (BB*TT)          // 65536
#define M_BN (BB*NN)          // 32768

// ---------------- device scratch (static globals; no allocation) ----------------
__device__ float g_trimean[(long)M_BT * DN];          //  26 MB (tf32-rounded)
__device__ float g_x      [(long)M_BT * DH];          //  79 MB (tf32-rounded)
__device__ float g_big    [(long)M_BT * 6 * DH];      // 472 MB (gi; later scores)
__device__ float g_hidden [(long)M_BT * 2 * DH];      // 157 MB (tf32-rounded)
__device__ float g_hid    [(long)M_BT * DH];          //  79 MB (tf32-rounded)
__device__ float g_alpha  [(long)BB * TT];
__device__ float g_Wih    [2 * 3 * DH * DH];          // concat + tf32-rounded
__device__ float g_bih    [2 * 3 * DH];               // concat (fp32, epilogue-only)
__device__ float g_ctx_r  [(long)BB * LQ * DH];       //  39 MB tf32-rounded ctx
__device__ float g_nodes_r[(long)M_BN * DN];          //  13 MB tf32-rounded nodes
__device__ float g_wmean_r[DH * DN];
__device__ float g_wout_r [DH * 2 * DH];
__device__ float g_wnode_r[DH * DN];
__device__ float g_zero_bias[2048];                   // zero-initialized

__device__ __forceinline__ float tf32r(float x) {
    float y;
    asm("cvt.rna.tf32.f32 %0, %1;" : "=f"(y) : "f"(x));
    return y;
}

// =======================================================================
// tf32 mma.sync GEMM, cp.async 3-stage pipeline. All operands PRE-ROUNDED
// to tf32 in gmem, so the hot loop has NO cvt.
//   C[M,N] = A[M,K] * B[N,K]^T + bias  (opt tanh, opt tf32-round output)
// CTA tile 128x128, BK=16, 256 threads (8 warps, 2x4), warp tile 64x32.
// grid.x = N tiles (fast; shares A slab via L2), grid.y = M tiles.
// M % 128 == 0; K % 4 == 0; N arbitrary.
// =======================================================================

#define SM_STRIDE 20                    // floats/row, conflict-free frag pattern
#define BUF_FLOATS (128 * SM_STRIDE)    // 2560 floats per tile buffer
#define GEMM_SMEM  (6 * BUF_FLOATS * 4) // 3 bufs A + 3 bufs B = 61440 bytes

template<bool TANH, bool ROUND_OUT>
__global__ void __launch_bounds__(256)
mma_gemm_kernel(const float* __restrict__ A, const float* __restrict__ Bm,
                const float* __restrict__ bias, float* __restrict__ C,
                int M, int N, int K,
                long strideA, long strideB, long strideC)
{
    extern __shared__ float dsm[];      // [3][128][20] A, then [3][128][20] B

    const int batch = blockIdx.z;
    A  += (long)batch * strideA;
    Bm += (long)batch * strideB;
    C  += (long)batch * strideC;

    const int tid   = threadIdx.x;           // 0..255
    const int wid   = tid >> 5;
    const int lane  = tid & 31;
    const int warpM = wid >> 2;              // 0..1
    const int warpN = wid & 3;               // 0..3
    const int g     = lane >> 2;             // 0..7
    const int t4    = lane & 3;              // 0..3

    const int rowBase = blockIdx.y * 128;    // M tile
    const int colBase = blockIdx.x * 128;    // N tile (fast-varying)

    const int fr = tid >> 2;                 // 0..63
    const int fq = tid & 3;                  // 16B chunk in row

    float c[4][4][4];
    #pragma unroll
    for (int mt = 0; mt < 4; mt++)
        #pragma unroll
        for (int nt = 0; nt < 4; nt++)
            #pragma unroll
            for (int q = 0; q < 4; q++) c[mt][nt][q] = 0.f;

    const int nStages = (K + 15) / 16;

    auto load_stage = [&](int s) {
        const int buf = s % 3;
        float* as = dsm + buf * BUF_FLOATS;
        float* bs = dsm + (3 + buf) * BUF_FLOATS;
        const int gk = s * 16 + fq * 4;
        #pragma unroll
        for (int it = 0; it < 2; it++) {
            int r = fr + it * 64;
            {
                uint32_t dst = (uint32_t)__cvta_generic_to_shared(&as[r * SM_STRIDE + fq * 4]);
                const float* src = (gk < K) ? &A[(long)(rowBase + r) * K + gk] : A;
                int sz = (gk < K) ? 16 : 0;
                asm volatile("cp.async.ca.shared.global [%0], [%1], 16, %2;"
                             :: "r"(dst), "l"(src), "r"(sz));
            }
            {
                int gn = colBase + r;
                bool ok = (gn < N) && (gk < K);
                uint32_t dst = (uint32_t)__cvta_generic_to_shared(&bs[r * SM_STRIDE + fq * 4]);
                const float* src = ok ? &Bm[(long)gn * K + gk] : Bm;
                int sz = ok ? 16 : 0;
                asm volatile("cp.async.ca.shared.global [%0], [%1], 16, %2;"
                             :: "r"(dst), "l"(src), "r"(sz));
            }
        }
        asm volatile("cp.async.commit_group;");
    };

    load_stage(0);
    if (nStages > 1) load_stage(1);

    for (int s = 0; s < nStages; s++) {
        if (s + 1 < nStages) asm volatile("cp.async.wait_group 1;");
        else                 asm volatile("cp.async.wait_group 0;");
        __syncthreads();

        const float* as = dsm + (s % 3) * BUF_FLOATS;
        const float* bs = dsm + (3 + s % 3) * BUF_FLOATS;

        #pragma unroll
        for (int kk = 0; kk < 16; kk += 8) {
            uint32_t ar[4][4], br[4][2];
            #pragma unroll
            for (int mt = 0; mt < 4; mt++) {
                int r0 = warpM * 64 + mt * 16 + g;
                ar[mt][0] = __float_as_uint(as[(r0    ) * SM_STRIDE + kk + t4    ]);
                ar[mt][1] = __float_as_uint(as[(r0 + 8) * SM_STRIDE + kk + t4    ]);
                ar[mt][2] = __float_as_uint(as[(r0    ) * SM_STRIDE + kk + t4 + 4]);
                ar[mt][3] = __float_as_uint(as[(r0 + 8) * SM_STRIDE + kk + t4 + 4]);
            }
            #pragma unroll
            for (int nt = 0; nt < 4; nt++) {
                int n0 = warpN * 32 + nt * 8 + g;
                br[nt][0] = __float_as_uint(bs[n0 * SM_STRIDE + kk + t4    ]);
                br[nt][1] = __float_as_uint(bs[n0 * SM_STRIDE + kk + t4 + 4]);
            }
            #pragma unroll
            for (int mt = 0; mt < 4; mt++)
                #pragma unroll
                for (int nt = 0; nt < 4; nt++) {
                    asm volatile(
                        "mma.sync.aligned.m16n8k8.row.col.f32.tf32.tf32.f32 "
                        "{%0,%1,%2,%3}, {%4,%5,%6,%7}, {%8,%9}, {%0,%1,%2,%3};"
                        : "+f"(c[mt][nt][0]), "+f"(c[mt][nt][1]),
                          "+f"(c[mt][nt][2]), "+f"(c[mt][nt][3])
                        : "r"(ar[mt][0]), "r"(ar[mt][1]), "r"(ar[mt][2]), "r"(ar[mt][3]),
                          "r"(br[nt][0]), "r"(br[nt][1]));
                }
        }
        if (s + 2 < nStages) load_stage(s + 2);
    }

    // ---- epilogue: bias (+tanh) (+round), float2 stores ----
    #pragma unroll
    for (int mt = 0; mt < 4; mt++) {
        int r0 = rowBase + warpM * 64 + mt * 16 + g;
        #pragma unroll
        for (int nt = 0; nt < 4; nt++) {
            int col0 = colBase + warpN * 32 + nt * 8 + 2 * t4;
            if (col0 + 1 < N) {
                float b0 = bias[col0], b1 = bias[col0 + 1];
                float2 v0 = make_float2(c[mt][nt][0] + b0, c[mt][nt][1] + b1);
                float2 v1 = make_float2(c[mt][nt][2] + b0, c[mt][nt][3] + b1);
                if (TANH) {
                    v0.x = tanhf(v0.x); v0.y = tanhf(v0.y);
                    v1.x = tanhf(v1.x); v1.y = tanhf(v1.y);
                }
                if (ROUND_OUT) {
                    v0.x = tf32r(v0.x); v0.y = tf32r(v0.y);
                    v1.x = tf32r(v1.x); v1.y = tf32r(v1.y);
                }
                *reinterpret_cast<float2*>(&C[(long)r0 * N + col0]) = v0;
                *reinterpret_cast<float2*>(&C[(long)(r0 + 8) * N + col0]) = v1;
            } else if (col0 < N) {
                float b0 = bias[col0];
                float v0 = c[mt][nt][0] + b0;
                float v1 = c[mt][nt][2] + b0;
                if (TANH) { v0 = tanhf(v0); v1 = tanhf(v1); }
                if (ROUND_OUT) { v0 = tf32r(v0); v1 = tf32r(v1); }
                C[(long)r0 * N + col0] = v0;
                C[(long)(r0 + 8) * N + col0] = v1;
            }
        }
    }
}

// ---------------- tf32 round-copy (float4) ----------------
__global__ void round_copy_kernel(const float4* __restrict__ src,
                                  float4* __restrict__ dst, long n4)
{
    long i = (long)blockIdx.x * blockDim.x + threadIdx.x;
    if (i >= n4) return;
    float4 v = src[i];
    dst[i] = make_float4(tf32r(v.x), tf32r(v.y), tf32r(v.z), tf32r(v.w));
}

// ---------------- Wih concat + round (float4) ----------------
__global__ void wih_concat_kernel(const float4* __restrict__ Wf,
                                  const float4* __restrict__ Wb,
                                  float4* __restrict__ dst)
{
    const long half = (long)3 * DH * DH / 4;     // 67500
    long i = (long)blockIdx.x * blockDim.x + threadIdx.x;
    if (i >= 2 * half) return;
    float4 v = (i < half) ? Wf[i] : Wb[i - half];
    dst[i] = make_float4(tf32r(v.x), tf32r(v.y), tf32r(v.z), tf32r(v.w));
}

// ---------------- gather + mean of head/tail node vectors (tf32-rounded) -------
__global__ void gather_mean_kernel(const float4* __restrict__ nodes,
                                   const int* __restrict__ trip,
                                   float4* __restrict__ out)
{
    long idx = (long)blockIdx.x * blockDim.x + threadIdx.x;
    long total = (long)M_BT * (DN / 4);
    if (idx >= total) return;
    int d4 = (int)(idx % (DN / 4));
    long bt = idx / (DN / 4);
    int b = (int)(bt / TT);
    int t = (int)(bt % TT);
    int h  = trip[((long)b * TT + t) * 3 + 0];
    int tl = trip[((long)b * TT + t) * 3 + 2];
    float4 vh = nodes[((long)b * NN + h)  * (DN / 4) + d4];
    float4 vt = nodes[((long)b * NN + tl) * (DN / 4) + d4];
    out[idx] = make_float4(tf32r(0.5f * (vh.x + vt.x)), tf32r(0.5f * (vh.y + vt.y)),
                           tf32r(0.5f * (vh.z + vt.z)), tf32r(0.5f * (vh.w + vt.w)));
}

// ---------------- combined GRU gate activation, float4, tf32-rounded out -------
__device__ __forceinline__ float4 sig4(float4 a) {
    return make_float4(1.f / (1.f + expf(-a.x)), 1.f / (1.f + expf(-a.y)),
                       1.f / (1.f + expf(-a.z)), 1.f / (1.f + expf(-a.w)));
}
__global__ void gru_act2_kernel(const float4* __restrict__ gi,
                                const float4* __restrict__ b_hh_f,
                                const float4* __restrict__ b_hh_b,
                                float4* __restrict__ hidden)
{
    long idx = (long)blockIdx.x * blockDim.x + threadIdx.x;   // over M_BT*150
    long total = (long)M_BT * (2 * DH / 4);
    if (idx >= total) return;
    long i = idx / 150;
    int  c4 = (int)(idx % 150);
    int dir = c4 / 75;
    int j4  = c4 % 75;
    const float4* gir = gi + i * 450 + (long)dir * 225;
    const float4* bh  = dir ? b_hh_b : b_hh_f;
    float4 R = gir[j4],      br = bh[j4];
    float4 Z = gir[75 + j4], bz = bh[75 + j4];
    float4 Nv = gir[150 + j4], bn = bh[150 + j4];
    float4 rr = sig4(make_float4(R.x + br.x, R.y + br.y, R.z + br.z, R.w + br.w));
    float4 zz = sig4(make_float4(Z.x + bz.x, Z.y + bz.y, Z.z + bz.z, Z.w + bz.w));
    float4 nn = make_float4(tanhf(Nv.x + rr.x * bn.x), tanhf(Nv.y + rr.y * bn.y),
                            tanhf(Nv.z + rr.z * bn.z), tanhf(Nv.w + rr.w * bn.w));
    hidden[i * 150 + c4] = make_float4(tf32r((1.f - zz.x) * nn.x),
                                       tf32r((1.f - zz.y) * nn.y),
                                       tf32r((1.f - zz.z) * nn.z),
                                       tf32r((1.f - zz.w) * nn.w));
}

// ---------------- per-row softmax + atomic alpha accumulation ----------------
__global__ void softmax_row_kernel(const float* __restrict__ S,
                                   float* __restrict__ alpha)
{
    int l = blockIdx.x, b = blockIdx.y;
    int t = threadIdx.x;                 // 0..511
    __shared__ float red[16];
    __shared__ float bcast;
    const float* row = S + ((long)b * LQ + l) * TT;
    float s = row[t];

    float m = s;
    #pragma unroll
    for (int o = 16; o > 0; o >>= 1) m = fmaxf(m, __shfl_xor_sync(0xffffffffu, m, o));
    if ((t & 31) == 0) red[t >> 5] = m;
    __syncthreads();
    if (t < 16) {
        float v = red[t];
        #pragma unroll
        for (int o = 8; o > 0; o >>= 1) v = fmaxf(v, __shfl_xor_sync(0xffffu, v, o));
        if (t == 0) bcast = v;
    }
    __syncthreads();
    float bm = bcast;

    float e = expf(s - bm);
    float sm = e;
    #pragma unroll
    for (int o = 16; o > 0; o >>= 1) sm += __shfl_xor_sync(0xffffffffu, sm, o);
    if ((t & 31) == 0) red[t >> 5] = sm;
    __syncthreads();
    if (t < 16) {
        float v = red[t];
        #pragma unroll
        for (int o = 8; o > 0; o >>= 1) v += __shfl_xor_sync(0xffffu, v, o);
        if (t == 0) bcast = v;
    }
    __syncthreads();
    float tot = bcast;

    atomicAdd(&alpha[(long)b * TT + t], e / tot);
}

// ---------------- rep = alpha @ hid, then LayerNorm -> path_feature ----------------
__global__ void rep_ln_kernel(const float* __restrict__ hid,
                              const float* __restrict__ alpha,
                              const float* __restrict__ gamma,
                              const float* __restrict__ beta,
                              float* __restrict__ out)
{
    int b = blockIdx.x;
    int tid = threadIdx.x;        // 512
    __shared__ float a_s[TT];
    __shared__ float r_s[DH];
    __shared__ float red[32];
    a_s[tid] = alpha[(long)b * TT + tid];
    __syncthreads();
    if (tid < DH) {
        const float* hb = hid + (long)b * TT * DH;
        float v0 = 0.f, v1 = 0.f, v2 = 0.f, v3 = 0.f;
        float v4 = 0.f, v5 = 0.f, v6 = 0.f, v7 = 0.f;
        #pragma unroll 1
        for (int t = 0; t < TT; t += 8) {
            v0 = fmaf(a_s[t + 0], hb[(long)(t + 0) * DH + tid], v0);
            v1 = fmaf(a_s[t + 1], hb[(long)(t + 1) * DH + tid], v1);
            v2 = fmaf(a_s[t + 2], hb[(long)(t + 2) * DH + tid], v2);
            v3 = fmaf(a_s[t + 3], hb[(long)(t + 3) * DH + tid], v3);
            v4 = fmaf(a_s[t + 4], hb[(long)(t + 4) * DH + tid], v4);
            v5 = fmaf(a_s[t + 5], hb[(long)(t + 5) * DH + tid], v5);
            v6 = fmaf(a_s[t + 6], hb[(long)(t + 6) * DH + tid], v6);
            v7 = fmaf(a_s[t + 7], hb[(long)(t + 7) * DH + tid], v7);
        }
        r_s[tid] = ((v0 + v1) + (v2 + v3)) + ((v4 + v5) + (v6 + v7));
    }
    __syncthreads();
    float p  = (tid < DH) ? r_s[tid] : 0.f;
    float p2 = p * p;
    #pragma unroll
    for (int o = 16; o > 0; o >>= 1) {
        p  += __shfl_xor_sync(0xffffffffu, p,  o);
        p2 += __shfl_xor_sync(0xffffffffu, p2, o);
    }
    if ((tid & 31) == 0) { red[tid >> 5] = p; red[16 + (tid >> 5)] = p2; }
    __syncthreads();
    float mean = 0.f, m2 = 0.f;
    #pragma unroll
    for (int w = 0; w < 16; w++) { mean += red[w]; m2 += red[16 + w]; }
    mean /= (float)DH; m2 /= (float)DH;
    float var = m2 - mean * mean;
    if (tid < DH)
        out[(long)b * DH + tid] =
            (r_s[tid] - mean) * rsqrtf(var + EPS) * gamma[tid] + beta[tid];
}

// ---------------- zero-fill ----------------
__global__ void zero_kernel(float* __restrict__ p, long n)
{
    long i = (long)blockIdx.x * blockDim.x + threadIdx.x;
    if (i < n) p[i] = 0.f;
}

// ---------------- host launcher ----------------
extern "C" void kernel_launch(void* const* d_in, const int* in_sizes, int n_in,
                              void* d_out, int out_size)
{
    const float* nodes   = (const float*)d_in[0];
    const float* ctx     = (const float*)d_in[1];
    const int*   trip    = (const int*)  d_in[2];
    // d_in[3] = node_number (compile-time constant NN = 256)
    const float* W_mean  = (const float*)d_in[4];
    const float* b_mean  = (const float*)d_in[5];
    const float* W_ih_f  = (const float*)d_in[6];
    const float* b_ih_f  = (const float*)d_in[7];
    const float* b_hh_f  = (const float*)d_in[8];
    const float* W_ih_b  = (const float*)d_in[9];
    const float* b_ih_b  = (const float*)d_in[10];
    const float* b_hh_b  = (const float*)d_in[11];
    const float* W_out   = (const float*)d_in[12];
    const float* b_out   = (const float*)d_in[13];
    const float* W_node  = (const float*)d_in[14];
    const float* b_node  = (const float*)d_in[15];
    const float* gamma   = (const float*)d_in[16];
    const float* beta    = (const float*)d_in[17];
    float* out = (float*)d_out;

    float *p_trimean, *p_x, *p_big, *p_hidden, *p_hid, *p_alpha, *p_Wih, *p_bih;
    float *p_ctx, *p_nodes, *p_wmean, *p_wout, *p_wnode, *p_zb;
    cudaGetSymbolAddress((void**)&p_trimean, g_trimean);
    cudaGetSymbolAddress((void**)&p_x,       g_x);
    cudaGetSymbolAddress((void**)&p_big,     g_big);
    cudaGetSymbolAddress((void**)&p_hidden,  g_hidden);
    cudaGetSymbolAddress((void**)&p_hid,     g_hid);
    cudaGetSymbolAddress((void**)&p_alpha,   g_alpha);
    cudaGetSymbolAddress((void**)&p_Wih,     g_Wih);
    cudaGetSymbolAddress((void**)&p_bih,     g_bih);
    cudaGetSymbolAddress((void**)&p_ctx,     g_ctx_r);
    cudaGetSymbolAddress((void**)&p_nodes,   g_nodes_r);
    cudaGetSymbolAddress((void**)&p_wmean,   g_wmean_r);
    cudaGetSymbolAddress((void**)&p_wout,    g_wout_r);
    cudaGetSymbolAddress((void**)&p_wnode,   g_wnode_r);
    cudaGetSymbolAddress((void**)&p_zb,      g_zero_bias);

    float* p_gi     = p_big;   // [M_BT, 1800]  GRU phase
    float* p_scores = p_big;   // [B, LQ, TT]   attention phase (disjoint lifetime)

    // opt-in to 60KB dynamic smem (idempotent)
    cudaFuncSetAttribute(mma_gemm_kernel<false, false>,
                         cudaFuncAttributeMaxDynamicSharedMemorySize, GEMM_SMEM);
    cudaFuncSetAttribute(mma_gemm_kernel<false, true>,
                         cudaFuncAttributeMaxDynamicSharedMemorySize, GEMM_SMEM);
    cudaFuncSetAttribute(mma_gemm_kernel<true, true>,
                         cudaFuncAttributeMaxDynamicSharedMemorySize, GEMM_SMEM);

    // 0) prepare tf32-rounded operands
    {
        wih_concat_kernel<<<(2 * 67500 + 255) / 256, 256>>>(
            (const float4*)W_ih_f, (const float4*)W_ih_b, (float4*)p_Wih);
        cudaMemcpyAsync(p_bih,          b_ih_f, (size_t)3 * DH * 4, cudaMemcpyDeviceToDevice);
        cudaMemcpyAsync(p_bih + 3 * DH, b_ih_b, (size_t)3 * DH * 4, cudaMemcpyDeviceToDevice);
        long n4;
        n4 = (long)BB * LQ * DH / 4;
        round_copy_kernel<<<(unsigned)((n4 + 255) / 256), 256>>>((const float4*)ctx, (float4*)p_ctx, n4);
        n4 = (long)M_BN * DN / 4;
        round_copy_kernel<<<(unsigned)((n4 + 255) / 256), 256>>>((const float4*)nodes, (float4*)p_nodes, n4);
        n4 = DH * DN / 4;
        round_copy_kernel<<<(unsigned)((n4 + 255) / 256), 256>>>((const float4*)W_mean, (float4*)p_wmean, n4);
        round_copy_kernel<<<(unsigned)((n4 + 255) / 256), 256>>>((const float4*)W_node, (float4*)p_wnode, n4);
        n4 = DH * 2 * DH / 4;
        round_copy_kernel<<<(unsigned)((n4 + 255) / 256), 256>>>((const float4*)W_out, (float4*)p_wout, n4);
    }

    // 1) tri_mean gather (tf32-rounded output)
    {
        long total = (long)M_BT * (DN / 4);
        gather_mean_kernel<<<(unsigned)((total + 255) / 256), 256>>>(
            (const float4*)nodes, trip, (float4*)p_trimean);
    }
    // 2) x = tri_mean @ W_mean^T + b_mean      [65536,300] K=100  (round out)
    {
        dim3 g((DH + 127) / 128, M_BT / 128, 1);
        mma_gemm_kernel<false, true><<<g, 256, GEMM_SMEM>>>(p_trimean, p_wmean, b_mean, p_x,
                                                            M_BT, DH, DN, 0, 0, 0);
    }
    // 3) both GRU directions: gi = x @ Wih^T + bih   [65536,1800] K=300
    {
        dim3 g((6 * DH + 127) / 128, M_BT / 128, 1);
        mma_gemm_kernel<false, false><<<g, 256, GEMM_SMEM>>>(p_x, p_Wih, p_bih, p_gi,
                                                             M_BT, 6 * DH, DH, 0, 0, 0);
    }
    // 4) gate activation -> hidden [65536,600] (tf32-rounded)
    {
        long total = (long)M_BT * (2 * DH / 4);
        gru_act2_kernel<<<(unsigned)((total + 255) / 256), 256>>>(
            (const float4*)p_gi, (const float4*)b_hh_f, (const float4*)b_hh_b,
            (float4*)p_hidden);
    }
    // 5) hid_ = tanh(hidden @ W_out^T + b_out)  [65536,300] K=600  (round out)
    {
        dim3 g((DH + 127) / 128, M_BT / 128, 1);
        mma_gemm_kernel<true, true><<<g, 256, GEMM_SMEM>>>(p_hidden, p_wout, b_out, p_hid,
                                                           M_BT, DH, 2 * DH, 0, 0, 0);
    }
    // 6) scores[b] = ctx_r[b] @ hid_[b]^T   (batched: M=256, N=512, K=300)
    {
        dim3 g(TT / 128, LQ / 128, BB);
        mma_gemm_kernel<false, false><<<g, 256, GEMM_SMEM>>>(p_ctx, p_hid, p_zb, p_scores,
                                                             LQ, TT, DH,
                                                             (long)LQ * DH, (long)TT * DH,
                                                             (long)LQ * TT);
    }
    // 7) alpha = sum_l softmax_t(scores)
    {
        long an = (long)BB * TT;
        zero_kernel<<<(unsigned)((an + 255) / 256), 256>>>(p_alpha, an);
        dim3 g(LQ, BB);
        softmax_row_kernel<<<g, TT>>>(p_scores, p_alpha);
    }
    // 8) rep + LayerNorm -> path_feature (out offset 0)
    rep_ln_kernel<<<BB, TT>>>(p_hid, p_alpha, gamma, beta, out);
    // 9) node_feature = nodes_r @ W_node^T + b_node -> out offset B*DH
    {
        dim3 g((DH + 127) / 128, M_BN / 128, 1);
        mma_gemm_kernel<false, false><<<g, 256, GEMM_SMEM>>>(p_nodes, p_wnode, b_node,
                                                             out + (long)BB * DH,
                                                             M_BN, DH, DN, 0, 0, 0);
    }
    // 10) node_mask zeros, if the output buffer includes it
    {
        long mask_off = (long)BB * DH + (long)M_BN * DH;   // 9,868,800
        long mask_n   = (long)BB * NN;                     // 32,768
        if ((long)out_size >= mask_off + mask_n) {
            zero_kernel<<<(unsigned)((mask_n + 255) / 256), 256>>>(out + mask_off, mask_n);
        }
    }
}

// round 11
// speedup vs baseline: 9.0750x; 1.4608x over previous
#include <cuda_runtime.h>
#include <cuda_fp16.h>
#include <math.h>
#include <stdint.h>

// ---------------- problem constants ----------------
#define BB   128      // batch
#define TT   512      // triples per dialogue
#define LQ   256      // query length
#define NN   256      // nodes per dialogue
#define DN   100      // node dim
#define DH   300      // hidden dim
#define EPS  1e-5f

#define M_BT (BB*TT)          // 65536
#define M_BN (BB*NN)          // 32768

// padded K dims (multiples of 8 halves = 16B)
#define P_DN   104
#define P_DH   304
#define P_2DH  608
#define P_6DH  1808

// ---------------- device scratch (static globals; no allocation) ----------------
__device__ __half g_tri_h  [(long)M_BT * P_DN];       // 13.6 MB
__device__ __half g_x_h    [(long)M_BT * P_DH];       // 39.8 MB
__device__ float  g_big    [(long)M_BT * P_6DH / 2];  // 237 MB: gi (half) then scores (float)
__device__ __half g_hidden_h[(long)M_BT * P_2DH];     // 79.7 MB
__device__ __half g_hid_h  [(long)M_BT * P_DH];       // 39.8 MB
__device__ __half g_ctx_h  [(long)BB * LQ * P_DH];    // 19.9 MB
__device__ __half g_nodes_h[(long)M_BN * P_DN];       //  6.8 MB
__device__ __half g_wmean_h[DH * P_DN];
__device__ __half g_wout_h [DH * P_2DH];
__device__ __half g_wnode_h[DH * P_DN];
__device__ __half g_wih_h  [2 * 3 * DH * P_DH];       // concat fwd;bwd [1800,304]
__device__ float  g_bih    [2 * 3 * DH];
__device__ float  g_alpha  [(long)BB * TT];
__device__ float  g_zero_bias[2048];                  // zero-initialized

// =======================================================================
// fp16 mma.sync GEMM (m16n8k16, fp32 accum), cp.async 3-stage pipeline.
//   C[M,N] = A[M,Kpad] * B[N,Kpad]^T + bias  (opt tanh; half or float out)
// Operands pre-converted to fp16 with zero-padded K rows (lda/ldb = Kpad,
// multiple of 8 -> every cp.async is an aligned full 16B).
// CTA tile 128x128, BK=32 halves, 256 threads (8 warps 2x4), warp 64x32.
// grid.x = N tiles (fast), grid.y = M tiles. M % 128 == 0.
// HALF_OUT: cols [N, ldc) are zero-filled (keeps downstream pads clean).
// =======================================================================

#define HSTR 40                    // halves per smem row (conflict-free)
#define HBUF (128 * HSTR)          // 5120 halves per tile buffer
#define GEMM_SMEM (6 * HBUF * 2)   // 3 A bufs + 3 B bufs = 61440 bytes

template<bool TANH, bool HALF_OUT>
__global__ void __launch_bounds__(256)
mma_gemm_kernel(const __half* __restrict__ A, const __half* __restrict__ Bm,
                const float* __restrict__ bias, void* __restrict__ Cv,
                int M, int N, int Kpad, int lda, int ldb, int ldc,
                long strideA, long strideB, long strideC)
{
    extern __shared__ __half hsm[];   // [3][128][HSTR] A, then [3][128][HSTR] B

    const int batch = blockIdx.z;
    A  += (long)batch * strideA;
    Bm += (long)batch * strideB;

    const int tid   = threadIdx.x;           // 0..255
    const int wid   = tid >> 5;
    const int lane  = tid & 31;
    const int warpM = wid >> 2;              // 0..1
    const int warpN = wid & 3;               // 0..3
    const int g     = lane >> 2;             // 0..7
    const int t4    = lane & 3;              // 0..3

    const int rowBase = blockIdx.y * 128;
    const int colBase = blockIdx.x * 128;

    const int fr = tid >> 2;                 // 0..63
    const int fq = tid & 3;                  // 16B chunk in 64B row

    float c[4][4][4];
    #pragma unroll
    for (int mt = 0; mt < 4; mt++)
        #pragma unroll
        for (int nt = 0; nt < 4; nt++)
            #pragma unroll
            for (int q = 0; q < 4; q++) c[mt][nt][q] = 0.f;

    const int nStages = (Kpad + 31) / 32;

    auto load_stage = [&](int s) {
        const int buf = s % 3;
        __half* as = hsm + buf * HBUF;
        __half* bs = hsm + (3 + buf) * HBUF;
        const int gk = s * 32 + fq * 8;      // half index
        #pragma unroll
        for (int it = 0; it < 2; it++) {
            int r = fr + it * 64;
            {
                uint32_t dst = (uint32_t)__cvta_generic_to_shared(&as[r * HSTR + fq * 8]);
                const __half* src = (gk < Kpad) ? &A[(long)(rowBase + r) * lda + gk] : A;
                int sz = (gk < Kpad) ? 16 : 0;
                asm volatile("cp.async.ca.shared.global [%0], [%1], 16, %2;"
                             :: "r"(dst), "l"(src), "r"(sz));
            }
            {
                int gn = colBase + r;
                bool ok = (gn < N) && (gk < Kpad);
                uint32_t dst = (uint32_t)__cvta_generic_to_shared(&bs[r * HSTR + fq * 8]);
                const __half* src = ok ? &Bm[(long)gn * ldb + gk] : Bm;
                int sz = ok ? 16 : 0;
                asm volatile("cp.async.ca.shared.global [%0], [%1], 16, %2;"
                             :: "r"(dst), "l"(src), "r"(sz));
            }
        }
        asm volatile("cp.async.commit_group;");
    };

    load_stage(0);
    if (nStages > 1) load_stage(1);

    for (int s = 0; s < nStages; s++) {
        if (s + 1 < nStages) asm volatile("cp.async.wait_group 1;");
        else                 asm volatile("cp.async.wait_group 0;");
        __syncthreads();

        const __half* as = hsm + (s % 3) * HBUF;
        const __half* bs = hsm + (3 + s % 3) * HBUF;

        #pragma unroll
        for (int kk = 0; kk < 32; kk += 16) {
            uint32_t ar[4][4], br[4][2];
            #pragma unroll
            for (int mt = 0; mt < 4; mt++) {
                int r0 = warpM * 64 + mt * 16 + g;
                ar[mt][0] = *reinterpret_cast<const uint32_t*>(&as[(r0    ) * HSTR + kk + 2 * t4    ]);
                ar[mt][1] = *reinterpret_cast<const uint32_t*>(&as[(r0 + 8) * HSTR + kk + 2 * t4    ]);
                ar[mt][2] = *reinterpret_cast<const uint32_t*>(&as[(r0    ) * HSTR + kk + 2 * t4 + 8]);
                ar[mt][3] = *reinterpret_cast<const uint32_t*>(&as[(r0 + 8) * HSTR + kk + 2 * t4 + 8]);
            }
            #pragma unroll
            for (int nt = 0; nt < 4; nt++) {
                int n0 = warpN * 32 + nt * 8 + g;
                br[nt][0] = *reinterpret_cast<const uint32_t*>(&bs[n0 * HSTR + kk + 2 * t4    ]);
                br[nt][1] = *reinterpret_cast<const uint32_t*>(&bs[n0 * HSTR + kk + 2 * t4 + 8]);
            }
            #pragma unroll
            for (int mt = 0; mt < 4; mt++)
                #pragma unroll
                for (int nt = 0; nt < 4; nt++) {
                    asm volatile(
                        "mma.sync.aligned.m16n8k16.row.col.f32.f16.f16.f32 "
                        "{%0,%1,%2,%3}, {%4,%5,%6,%7}, {%8,%9}, {%0,%1,%2,%3};"
                        : "+f"(c[mt][nt][0]), "+f"(c[mt][nt][1]),
                          "+f"(c[mt][nt][2]), "+f"(c[mt][nt][3])
                        : "r"(ar[mt][0]), "r"(ar[mt][1]), "r"(ar[mt][2]), "r"(ar[mt][3]),
                          "r"(br[nt][0]), "r"(br[nt][1]));
                }
        }
        if (s + 2 < nStages) load_stage(s + 2);
    }

    // ---- epilogue ----
    __half* Ch = (__half*)Cv + (HALF_OUT ? (long)batch * strideC : 0);
    float*  Cf = (float*)Cv + (HALF_OUT ? 0 : (long)batch * strideC);

    #pragma unroll
    for (int mt = 0; mt < 4; mt++) {
        int r0 = rowBase + warpM * 64 + mt * 16 + g;
        #pragma unroll
        for (int nt = 0; nt < 4; nt++) {
            int col0 = colBase + warpN * 32 + nt * 8 + 2 * t4;
            if (col0 + 1 < N) {
                float b0 = bias[col0], b1 = bias[col0 + 1];
                float v00 = c[mt][nt][0] + b0, v01 = c[mt][nt][1] + b1;
                float v10 = c[mt][nt][2] + b0, v11 = c[mt][nt][3] + b1;
                if (TANH) {
                    v00 = tanhf(v00); v01 = tanhf(v01);
                    v10 = tanhf(v10); v11 = tanhf(v11);
                }
                if (HALF_OUT) {
                    *reinterpret_cast<__half2*>(&Ch[(long)r0 * ldc + col0]) =
                        __floats2half2_rn(v00, v01);
                    *reinterpret_cast<__half2*>(&Ch[(long)(r0 + 8) * ldc + col0]) =
                        __floats2half2_rn(v10, v11);
                } else {
                    *reinterpret_cast<float2*>(&Cf[(long)r0 * ldc + col0]) = make_float2(v00, v01);
                    *reinterpret_cast<float2*>(&Cf[(long)(r0 + 8) * ldc + col0]) = make_float2(v10, v11);
                }
            } else {
                #pragma unroll
                for (int s2 = 0; s2 < 2; s2++) {
                    int cc = col0 + s2;
                    if (HALF_OUT) {
                        if (cc < ldc) {
                            float v0 = 0.f, v1 = 0.f;
                            if (cc < N) {
                                float bb = bias[cc];
                                v0 = c[mt][nt][0 + s2] + bb;
                                v1 = c[mt][nt][2 + s2] + bb;
                                if (TANH) { v0 = tanhf(v0); v1 = tanhf(v1); }
                            }
                            Ch[(long)r0 * ldc + cc] = __float2half_rn(v0);
                            Ch[(long)(r0 + 8) * ldc + cc] = __float2half_rn(v1);
                        }
                    } else {
                        if (cc < N) {
                            float bb = bias[cc];
                            float v0 = c[mt][nt][0 + s2] + bb;
                            float v1 = c[mt][nt][2 + s2] + bb;
                            if (TANH) { v0 = tanhf(v0); v1 = tanhf(v1); }
                            Cf[(long)r0 * ldc + cc] = v0;
                            Cf[(long)(r0 + 8) * ldc + cc] = v1;
                        }
                    }
                }
            }
        }
    }
}

// ---------------- fp32 -> padded fp16 convert ----------------
__global__ void f2h_pad_kernel(const float* __restrict__ src, __half* __restrict__ dst,
                               long rows, int K, int Kpad)
{
    long n2 = rows * (Kpad / 2);
    long i = (long)blockIdx.x * blockDim.x + threadIdx.x;
    if (i >= n2) return;
    int  c2 = (int)(i % (Kpad / 2));
    long r  = i / (Kpad / 2);
    int col = 2 * c2;
    __half2 h;
    if (col < K) {
        float2 v = *reinterpret_cast<const float2*>(&src[r * K + col]);
        h = __floats2half2_rn(v.x, v.y);
    } else {
        h = __floats2half2_rn(0.f, 0.f);
    }
    *reinterpret_cast<__half2*>(&dst[r * Kpad + col]) = h;
}

// ---------------- gather + mean, padded fp16 out ----------------
__global__ void gather_mean_kernel(const float* __restrict__ nodes,
                                   const int* __restrict__ trip,
                                   __half* __restrict__ out)
{
    long total = (long)M_BT * (P_DN / 2);
    long idx = (long)blockIdx.x * blockDim.x + threadIdx.x;
    if (idx >= total) return;
    int  c2 = (int)(idx % (P_DN / 2));
    long bt = idx / (P_DN / 2);
    int col = 2 * c2;
    int b = (int)(bt / TT);
    __half2 o;
    if (col < DN) {
        int h  = trip[bt * 3 + 0];
        int tl = trip[bt * 3 + 2];
        float2 vh = *reinterpret_cast<const float2*>(&nodes[((long)b * NN + h)  * DN + col]);
        float2 vt = *reinterpret_cast<const float2*>(&nodes[((long)b * NN + tl) * DN + col]);
        o = __floats2half2_rn(0.5f * (vh.x + vt.x), 0.5f * (vh.y + vt.y));
    } else {
        o = __floats2half2_rn(0.f, 0.f);
    }
    *reinterpret_cast<__half2*>(&out[bt * P_DN + col]) = o;
}

// ---------------- GRU gate activation: gi(half) -> hidden(half, padded) ------
__global__ void gru_act2_kernel(const __half* __restrict__ gi,
                                const float* __restrict__ bhf,
                                const float* __restrict__ bhb,
                                __half* __restrict__ hidden)
{
    long total = (long)M_BT * (P_2DH / 2);
    long idx = (long)blockIdx.x * blockDim.x + threadIdx.x;
    if (idx >= total) return;
    int  c2 = (int)(idx % (P_2DH / 2));
    long i  = idx / (P_2DH / 2);
    int col = 2 * c2;
    __half2 res;
    if (col < 2 * DH) {
        int dir = col / DH;
        int j   = col - dir * DH;         // even
        const __half* gg = gi + i * P_6DH + (long)dir * (3 * DH);
        const float*  bh = dir ? bhb : bhf;
        float2 R = __half22float2(*reinterpret_cast<const __half2*>(&gg[j]));
        float2 Z = __half22float2(*reinterpret_cast<const __half2*>(&gg[DH + j]));
        float2 Nv = __half22float2(*reinterpret_cast<const __half2*>(&gg[2 * DH + j]));
        float r0 = 1.f / (1.f + expf(-(R.x + bh[j])));
        float r1 = 1.f / (1.f + expf(-(R.y + bh[j + 1])));
        float z0 = 1.f / (1.f + expf(-(Z.x + bh[DH + j])));
        float z1 = 1.f / (1.f + expf(-(Z.y + bh[DH + j + 1])));
        float n0 = tanhf(Nv.x + r0 * bh[2 * DH + j]);
        float n1 = tanhf(Nv.y + r1 * bh[2 * DH + j + 1]);
        res = __floats2half2_rn((1.f - z0) * n0, (1.f - z1) * n1);
    } else {
        res = __floats2half2_rn(0.f, 0.f);
    }
    *reinterpret_cast<__half2*>(&hidden[i * P_2DH + col]) = res;
}

// ---------------- per-row softmax + atomic alpha accumulation ----------------
__global__ void softmax_row_kernel(const float* __restrict__ S,
                                   float* __restrict__ alpha)
{
    int l = blockIdx.x, b = blockIdx.y;
    int t = threadIdx.x;                 // 0..511
    __shared__ float red[16];
    __shared__ float bcast;
    const float* row = S + ((long)b * LQ + l) * TT;
    float s = row[t];

    float m = s;
    #pragma unroll
    for (int o = 16; o > 0; o >>= 1) m = fmaxf(m, __shfl_xor_sync(0xffffffffu, m, o));
    if ((t & 31) == 0) red[t >> 5] = m;
    __syncthreads();
    if (t < 16) {
        float v = red[t];
        #pragma unroll
        for (int o = 8; o > 0; o >>= 1) v = fmaxf(v, __shfl_xor_sync(0xffffu, v, o));
        if (t == 0) bcast = v;
    }
    __syncthreads();
    float bm = bcast;

    float e = expf(s - bm);
    float sm = e;
    #pragma unroll
    for (int o = 16; o > 0; o >>= 1) sm += __shfl_xor_sync(0xffffffffu, sm, o);
    if ((t & 31) == 0) red[t >> 5] = sm;
    __syncthreads();
    if (t < 16) {
        float v = red[t];
        #pragma unroll
        for (int o = 8; o > 0; o >>= 1) v += __shfl_xor_sync(0xffffu, v, o);
        if (t == 0) bcast = v;
    }
    __syncthreads();
    float tot = bcast;

    atomicAdd(&alpha[(long)b * TT + t], e / tot);
}

// ---------------- rep = alpha @ hid(half), then LayerNorm -> path_feature ------
__global__ void rep_ln_kernel(const __half* __restrict__ hid,
                              const float* __restrict__ alpha,
                              const float* __restrict__ gamma,
                              const float* __restrict__ beta,
                              float* __restrict__ out)
{
    int b = blockIdx.x;
    int tid = threadIdx.x;        // 512
    __shared__ float a_s[TT];
    __shared__ float r_s[DH];
    __shared__ float red[32];
    a_s[tid] = alpha[(long)b * TT + tid];
    __syncthreads();
    if (tid < DH) {
        const __half* hb = hid + (long)b * TT * P_DH;
        float v0 = 0.f, v1 = 0.f, v2 = 0.f, v3 = 0.f;
        #pragma unroll 1
        for (int t = 0; t < TT; t += 4) {
            v0 = fmaf(a_s[t + 0], __half2float(hb[(long)(t + 0) * P_DH + tid]), v0);
            v1 = fmaf(a_s[t + 1], __half2float(hb[(long)(t + 1) * P_DH + tid]), v1);
            v2 = fmaf(a_s[t + 2], __half2float(hb[(long)(t + 2) * P_DH + tid]), v2);
            v3 = fmaf(a_s[t + 3], __half2float(hb[(long)(t + 3) * P_DH + tid]), v3);
        }
        r_s[tid] = (v0 + v1) + (v2 + v3);
    }
    __syncthreads();
    float p  = (tid < DH) ? r_s[tid] : 0.f;
    float p2 = p * p;
    #pragma unroll
    for (int o = 16; o > 0; o >>= 1) {
        p  += __shfl_xor_sync(0xffffffffu, p,  o);
        p2 += __shfl_xor_sync(0xffffffffu, p2, o);
    }
    if ((tid & 31) == 0) { red[tid >> 5] = p; red[16 + (tid >> 5)] = p2; }
    __syncthreads();
    float mean = 0.f, m2 = 0.f;
    #pragma unroll
    for (int w = 0; w < 16; w++) { mean += red[w]; m2 += red[16 + w]; }
    mean /= (float)DH; m2 /= (float)DH;
    float var = m2 - mean * mean;
    if (tid < DH)
        out[(long)b * DH + tid] =
            (r_s[tid] - mean) * rsqrtf(var + EPS) * gamma[tid] + beta[tid];
}

// ---------------- zero-fill ----------------
__global__ void zero_kernel(float* __restrict__ p, long n)
{
    long i = (long)blockIdx.x * blockDim.x + threadIdx.x;
    if (i < n) p[i] = 0.f;
}

// ---------------- host launcher ----------------
extern "C" void kernel_launch(void* const* d_in, const int* in_sizes, int n_in,
                              void* d_out, int out_size)
{
    const float* nodes   = (const float*)d_in[0];
    const float* ctx     = (const float*)d_in[1];
    const int*   trip    = (const int*)  d_in[2];
    // d_in[3] = node_number (compile-time constant NN = 256)
    const float* W_mean  = (const float*)d_in[4];
    const float* b_mean  = (const float*)d_in[5];
    const float* W_ih_f  = (const float*)d_in[6];
    const float* b_ih_f  = (const float*)d_in[7];
    const float* b_hh_f  = (const float*)d_in[8];
    const float* W_ih_b  = (const float*)d_in[9];
    const float* b_ih_b  = (const float*)d_in[10];
    const float* b_hh_b  = (const float*)d_in[11];
    const float* W_out   = (const float*)d_in[12];
    const float* b_out   = (const float*)d_in[13];
    const float* W_node  = (const float*)d_in[14];
    const float* b_node  = (const float*)d_in[15];
    const float* gamma   = (const float*)d_in[16];
    const float* beta    = (const float*)d_in[17];
    float* out = (float*)d_out;

    __half *p_tri, *p_x, *p_hiddenh, *p_hidh, *p_ctxh, *p_nodesh;
    __half *p_wmean, *p_wout, *p_wnode, *p_wih;
    float *p_big, *p_alpha, *p_bih, *p_zb;
    cudaGetSymbolAddress((void**)&p_tri,     g_tri_h);
    cudaGetSymbolAddress((void**)&p_x,       g_x_h);
    cudaGetSymbolAddress((void**)&p_big,     g_big);
    cudaGetSymbolAddress((void**)&p_hiddenh, g_hidden_h);
    cudaGetSymbolAddress((void**)&p_hidh,    g_hid_h);
    cudaGetSymbolAddress((void**)&p_ctxh,    g_ctx_h);
    cudaGetSymbolAddress((void**)&p_nodesh,  g_nodes_h);
    cudaGetSymbolAddress((void**)&p_wmean,   g_wmean_h);
    cudaGetSymbolAddress((void**)&p_wout,    g_wout_h);
    cudaGetSymbolAddress((void**)&p_wnode,   g_wnode_h);
    cudaGetSymbolAddress((void**)&p_wih,     g_wih_h);
    cudaGetSymbolAddress((void**)&p_bih,     g_bih);
    cudaGetSymbolAddress((void**)&p_alpha,   g_alpha);
    cudaGetSymbolAddress((void**)&p_zb,      g_zero_bias);

    __half* p_gi     = (__half*)p_big;   // [M_BT, 1808] half, GRU phase
    float*  p_scores = p_big;            // [B, LQ, TT] float, attention phase

    cudaFuncSetAttribute(mma_gemm_kernel<false, true>,
                         cudaFuncAttributeMaxDynamicSharedMemorySize, GEMM_SMEM);
    cudaFuncSetAttribute(mma_gemm_kernel<true, true>,
                         cudaFuncAttributeMaxDynamicSharedMemorySize, GEMM_SMEM);
    cudaFuncSetAttribute(mma_gemm_kernel<false, false>,
                         cudaFuncAttributeMaxDynamicSharedMemorySize, GEMM_SMEM);

    // 0) operand conversion to padded fp16
    auto conv = [&](const float* s, __half* d, long rows, int K, int Kp) {
        long n2 = rows * (Kp / 2);
        f2h_pad_kernel<<<(unsigned)((n2 + 255) / 256), 256>>>(s, d, rows, K, Kp);
    };
    conv(W_ih_f, p_wih,                 3 * DH, DH, P_DH);
    conv(W_ih_b, p_wih + 3 * DH * P_DH, 3 * DH, DH, P_DH);
    conv(ctx,    p_ctxh,  (long)BB * LQ, DH, P_DH);
    conv(nodes,  p_nodesh, M_BN, DN, P_DN);
    conv(W_mean, p_wmean, DH, DN, P_DN);
    conv(W_node, p_wnode, DH, DN, P_DN);
    conv(W_out,  p_wout,  DH, 2 * DH, P_2DH);
    cudaMemcpyAsync(p_bih,          b_ih_f, (size_t)3 * DH * 4, cudaMemcpyDeviceToDevice);
    cudaMemcpyAsync(p_bih + 3 * DH, b_ih_b, (size_t)3 * DH * 4, cudaMemcpyDeviceToDevice);

    // 1) tri_mean gather -> half padded
    {
        long total = (long)M_BT * (P_DN / 2);
        gather_mean_kernel<<<(unsigned)((total + 255) / 256), 256>>>(nodes, trip, p_tri);
    }
    // 2) x = tri_mean @ W_mean^T + b_mean   [65536,300] Kpad=104 -> half [.,304]
    {
        dim3 g(3, M_BT / 128, 1);
        mma_gemm_kernel<false, true><<<g, 256, GEMM_SMEM>>>(
            p_tri, p_wmean, b_mean, p_x, M_BT, DH, P_DN, P_DN, P_DN, P_DH, 0, 0, 0);
    }
    // 3) gi = x @ Wih^T + bih   [65536,1800] Kpad=304 -> half [.,1808]
    {
        dim3 g(15, M_BT / 128, 1);
        mma_gemm_kernel<false, true><<<g, 256, GEMM_SMEM>>>(
            p_x, p_wih, p_bih, p_gi, M_BT, 6 * DH, P_DH, P_DH, P_DH, P_6DH, 0, 0, 0);
    }
    // 4) gate activation -> hidden half [65536,608]
    {
        long total = (long)M_BT * (P_2DH / 2);
        gru_act2_kernel<<<(unsigned)((total + 255) / 256), 256>>>(p_gi, b_hh_f, b_hh_b, p_hiddenh);
    }
    // 5) hid = tanh(hidden @ W_out^T + b_out)   [65536,300] Kpad=608 -> half [.,304]
    {
        dim3 g(3, M_BT / 128, 1);
        mma_gemm_kernel<true, true><<<g, 256, GEMM_SMEM>>>(
            p_hiddenh, p_wout, b_out, p_hidh, M_BT, DH, P_2DH, P_2DH, P_2DH, P_DH, 0, 0, 0);
    }
    // 6) scores[b] = ctx[b] @ hid[b]^T   (batched M=256,N=512,Kpad=304) -> float
    {
        dim3 g(4, LQ / 128, BB);
        mma_gemm_kernel<false, false><<<g, 256, GEMM_SMEM>>>(
            p_ctxh, p_hidh, p_zb, p_scores, LQ, TT, P_DH, P_DH, P_DH, TT,
            (long)LQ * P_DH, (long)TT * P_DH, (long)LQ * TT);
    }
    // 7) alpha = sum_l softmax_t(scores)
    {
        long an = (long)BB * TT;
        zero_kernel<<<(unsigned)((an + 255) / 256), 256>>>(p_alpha, an);
        dim3 g(LQ, BB);
        softmax_row_kernel<<<g, TT>>>(p_scores, p_alpha);
    }
    // 8) rep + LayerNorm -> path_feature (out offset 0)
    rep_ln_kernel<<<BB, TT>>>(p_hidh, p_alpha, gamma, beta, out);
    // 9) node_feature = nodes @ W_node^T + b_node -> float out at offset B*DH
    {
        dim3 g(3, M_BN / 128, 1);
        mma_gemm_kernel<false, false><<<g, 256, GEMM_SMEM>>>(
            p_nodesh, p_wnode, b_node, out + (long)BB * DH, M_BN, DH, P_DN, P_DN, P_DN, DH,
            0, 0, 0);
    }
    // 10) node_mask zeros, if the output buffer includes it
    {
        long mask_off = (long)BB * DH + (long)M_BN * DH;   // 9,868,800
        long mask_n   = (long)BB * NN;                     // 32,768
        if ((long)out_size >= mask_off + mask_n) {
            zero_kernel<<<(unsigned)((mask_n + 255) / 256), 256>>>(out + mask_off, mask_n);
        }
    }
}

// round 12
// speedup vs baseline: 10.9885x; 1.2109x over previous
#include <cuda_runtime.h>
#include <cuda_fp16.h>
#include <math.h>
#include <stdint.h>

// ---------------- problem constants ----------------
#define BB   128      // batch
#define TT   512      // triples per dialogue
#define LQ   256      // query length
#define NN   256      // nodes per dialogue
#define DN   100      // node dim
#define DH   300      // hidden dim
#define EPS  1e-5f

#define M_BT (BB*TT)          // 65536
#define M_BN (BB*NN)          // 32768

// padded K dims (multiples of 8 halves = 16B)
#define P_DN   104
#define P_DH   304
#define P_2DH  608
#define P_6DH  1808

// ---------------- device scratch (static globals; no allocation) ----------------
__device__ __half g_tri_h  [(long)M_BT * P_DN];       // 13.6 MB
__device__ float  g_big    [(long)M_BT * P_6DH / 2];  // 237 MB: gi (half) then scores (float)
__device__ __half g_hidden_h[(long)M_BT * P_2DH];     // 79.7 MB
__device__ __half g_hid_h  [(long)M_BT * P_DH];       // 39.8 MB
__device__ __half g_ctx_h  [(long)BB * LQ * P_DH];    // 19.9 MB
__device__ __half g_nodes_h[(long)M_BN * P_DN];       //  6.8 MB
__device__ __half g_wc_h   [6 * DH * P_DN];           // fused W_ih@W_mean [1800,104]
__device__ float  g_bc     [6 * DH];                  // fused bias
__device__ __half g_wout_h [DH * P_2DH];
__device__ __half g_wnode_h[DH * P_DN];
__device__ float  g_alpha  [(long)BB * TT];
__device__ float  g_zero_bias[2048];                  // zero-initialized

// =======================================================================
// fp16 mma.sync GEMM (m16n8k16, fp32 accum), cp.async 3-stage pipeline.
//   C[M,N] = A[M,Kpad] * B[N,Kpad]^T + bias  (opt tanh; half or float out)
// Operands pre-converted to fp16 with zero-padded K rows (lda/ldb = Kpad,
// multiple of 8 -> every cp.async is an aligned full 16B; src-size=0 form
// zero-fills smem for out-of-range chunks).
// CTA tile 128x128, BK=32 halves, 256 threads (8 warps 2x4), warp 64x32.
// grid.x = N tiles (fast), grid.y = M tiles. M % 128 == 0.
// HALF_OUT: cols [N, ldc) are zero-filled (keeps downstream pads clean).
// =======================================================================

#define HSTR 40                    // halves per smem row (conflict-free)
#define HBUF (128 * HSTR)          // 5120 halves per tile buffer
#define GEMM_SMEM (6 * HBUF * 2)   // 3 A bufs + 3 B bufs = 61440 bytes

template<bool TANH, bool HALF_OUT>
__global__ void __launch_bounds__(256)
mma_gemm_kernel(const __half* __restrict__ A, const __half* __restrict__ Bm,
                const float* __restrict__ bias, void* __restrict__ Cv,
                int M, int N, int Kpad, int lda, int ldb, int ldc,
                long strideA, long strideB, long strideC)
{
    extern __shared__ __half hsm[];   // [3][128][HSTR] A, then [3][128][HSTR] B

    const int batch = blockIdx.z;
    A  += (long)batch * strideA;
    Bm += (long)batch * strideB;

    const int tid   = threadIdx.x;           // 0..255
    const int wid   = tid >> 5;
    const int lane  = tid & 31;
    const int warpM = wid >> 2;              // 0..1
    const int warpN = wid & 3;               // 0..3
    const int g     = lane >> 2;             // 0..7
    const int t4    = lane & 3;              // 0..3

    const int rowBase = blockIdx.y * 128;
    const int colBase = blockIdx.x * 128;

    const int fr = tid >> 2;                 // 0..63
    const int fq = tid & 3;                  // 16B chunk in 64B row

    float c[4][4][4];
    #pragma unroll
    for (int mt = 0; mt < 4; mt++)
        #pragma unroll
        for (int nt = 0; nt < 4; nt++)
            #pragma unroll
            for (int q = 0; q < 4; q++) c[mt][nt][q] = 0.f;

    const int nStages = (Kpad + 31) / 32;

    auto load_stage = [&](int s) {
        const int buf = s % 3;
        __half* as = hsm + buf * HBUF;
        __half* bs = hsm + (3 + buf) * HBUF;
        const int gk = s * 32 + fq * 8;      // half index
        #pragma unroll
        for (int it = 0; it < 2; it++) {
            int r = fr + it * 64;
            {
                uint32_t dst = (uint32_t)__cvta_generic_to_shared(&as[r * HSTR + fq * 8]);
                const __half* src = (gk < Kpad) ? &A[(long)(rowBase + r) * lda + gk] : A;
                int sz = (gk < Kpad) ? 16 : 0;
                asm volatile("cp.async.ca.shared.global [%0], [%1], 16, %2;"
                             :: "r"(dst), "l"(src), "r"(sz));
            }
            {
                int gn = colBase + r;
                bool ok = (gn < N) && (gk < Kpad);
                uint32_t dst = (uint32_t)__cvta_generic_to_shared(&bs[r * HSTR + fq * 8]);
                const __half* src = ok ? &Bm[(long)gn * ldb + gk] : Bm;
                int sz = ok ? 16 : 0;
                asm volatile("cp.async.ca.shared.global [%0], [%1], 16, %2;"
                             :: "r"(dst), "l"(src), "r"(sz));
            }
        }
        asm volatile("cp.async.commit_group;");
    };

    load_stage(0);
    if (nStages > 1) load_stage(1);

    for (int s = 0; s < nStages; s++) {
        if (s + 1 < nStages) asm volatile("cp.async.wait_group 1;");
        else                 asm volatile("cp.async.wait_group 0;");
        __syncthreads();

        const __half* as = hsm + (s % 3) * HBUF;
        const __half* bs = hsm + (3 + s % 3) * HBUF;

        #pragma unroll
        for (int kk = 0; kk < 32; kk += 16) {
            uint32_t ar[4][4], br[4][2];
            #pragma unroll
            for (int mt = 0; mt < 4; mt++) {
                int r0 = warpM * 64 + mt * 16 + g;
                ar[mt][0] = *reinterpret_cast<const uint32_t*>(&as[(r0    ) * HSTR + kk + 2 * t4    ]);
                ar[mt][1] = *reinterpret_cast<const uint32_t*>(&as[(r0 + 8) * HSTR + kk + 2 * t4    ]);
                ar[mt][2] = *reinterpret_cast<const uint32_t*>(&as[(r0    ) * HSTR + kk + 2 * t4 + 8]);
                ar[mt][3] = *reinterpret_cast<const uint32_t*>(&as[(r0 + 8) * HSTR + kk + 2 * t4 + 8]);
            }
            #pragma unroll
            for (int nt = 0; nt < 4; nt++) {
                int n0 = warpN * 32 + nt * 8 + g;
                br[nt][0] = *reinterpret_cast<const uint32_t*>(&bs[n0 * HSTR + kk + 2 * t4    ]);
                br[nt][1] = *reinterpret_cast<const uint32_t*>(&bs[n0 * HSTR + kk + 2 * t4 + 8]);
            }
            #pragma unroll
            for (int mt = 0; mt < 4; mt++)
                #pragma unroll
                for (int nt = 0; nt < 4; nt++) {
                    asm volatile(
                        "mma.sync.aligned.m16n8k16.row.col.f32.f16.f16.f32 "
                        "{%0,%1,%2,%3}, {%4,%5,%6,%7}, {%8,%9}, {%0,%1,%2,%3};"
                        : "+f"(c[mt][nt][0]), "+f"(c[mt][nt][1]),
                          "+f"(c[mt][nt][2]), "+f"(c[mt][nt][3])
                        : "r"(ar[mt][0]), "r"(ar[mt][1]), "r"(ar[mt][2]), "r"(ar[mt][3]),
                          "r"(br[nt][0]), "r"(br[nt][1]));
                }
        }
        if (s + 2 < nStages) load_stage(s + 2);
    }

    // ---- epilogue ----
    __half* Ch = (__half*)Cv + (HALF_OUT ? (long)batch * strideC : 0);
    float*  Cf = (float*)Cv + (HALF_OUT ? 0 : (long)batch * strideC);

    #pragma unroll
    for (int mt = 0; mt < 4; mt++) {
        int r0 = rowBase + warpM * 64 + mt * 16 + g;
        #pragma unroll
        for (int nt = 0; nt < 4; nt++) {
            int col0 = colBase + warpN * 32 + nt * 8 + 2 * t4;
            if (col0 + 1 < N) {
                float b0 = bias[col0], b1 = bias[col0 + 1];
                float v00 = c[mt][nt][0] + b0, v01 = c[mt][nt][1] + b1;
                float v10 = c[mt][nt][2] + b0, v11 = c[mt][nt][3] + b1;
                if (TANH) {
                    v00 = tanhf(v00); v01 = tanhf(v01);
                    v10 = tanhf(v10); v11 = tanhf(v11);
                }
                if (HALF_OUT) {
                    *reinterpret_cast<__half2*>(&Ch[(long)r0 * ldc + col0]) =
                        __floats2half2_rn(v00, v01);
                    *reinterpret_cast<__half2*>(&Ch[(long)(r0 + 8) * ldc + col0]) =
                        __floats2half2_rn(v10, v11);
                } else {
                    *reinterpret_cast<float2*>(&Cf[(long)r0 * ldc + col0]) = make_float2(v00, v01);
                    *reinterpret_cast<float2*>(&Cf[(long)(r0 + 8) * ldc + col0]) = make_float2(v10, v11);
                }
            } else {
                #pragma unroll
                for (int s2 = 0; s2 < 2; s2++) {
                    int cc = col0 + s2;
                    if (HALF_OUT) {
                        if (cc < ldc) {
                            float v0 = 0.f, v1 = 0.f;
                            if (cc < N) {
                                float bb = bias[cc];
                                v0 = c[mt][nt][0 + s2] + bb;
                                v1 = c[mt][nt][2 + s2] + bb;
                                if (TANH) { v0 = tanhf(v0); v1 = tanhf(v1); }
                            }
                            Ch[(long)r0 * ldc + cc] = __float2half_rn(v0);
                            Ch[(long)(r0 + 8) * ldc + cc] = __float2half_rn(v1);
                        }
                    } else {
                        if (cc < N) {
                            float bb = bias[cc];
                            float v0 = c[mt][nt][0 + s2] + bb;
                            float v1 = c[mt][nt][2 + s2] + bb;
                            if (TANH) { v0 = tanhf(v0); v1 = tanhf(v1); }
                            Cf[(long)r0 * ldc + cc] = v0;
                            Cf[(long)(r0 + 8) * ldc + cc] = v1;
                        }
                    }
                }
            }
        }
    }
}

// ---------------- fused weight: Wc[i,d] = sum_j Wih[i,j] * W_mean[j,d] -------
__global__ void wc_weight_kernel(const float* __restrict__ Wf,
                                 const float* __restrict__ Wb,
                                 const float* __restrict__ Wm,
                                 __half* __restrict__ Wc)
{
    int idx = blockIdx.x * blockDim.x + threadIdx.x;   // over 1800 * P_DN
    if (idx >= 6 * DH * P_DN) return;
    int d = idx % P_DN;
    int i = idx / P_DN;
    __half h;
    if (d < DN) {
        const float* wr = (i < 3 * DH) ? &Wf[(long)i * DH] : &Wb[(long)(i - 3 * DH) * DH];
        float acc = 0.f;
        #pragma unroll 4
        for (int j = 0; j < DH; j++) acc = fmaf(wr[j], Wm[j * DN + d], acc);
        h = __float2half_rn(acc);
    } else {
        h = __float2half_rn(0.f);
    }
    Wc[idx] = h;
}

// ---------------- fused bias: bc[i] = bih[i] + sum_j Wih[i,j] * b_mean[j] ----
__global__ void wc_bias_kernel(const float* __restrict__ Wf,
                               const float* __restrict__ Wb,
                               const float* __restrict__ bm,
                               const float* __restrict__ bihf,
                               const float* __restrict__ bihb,
                               float* __restrict__ bc)
{
    int i = blockIdx.x * blockDim.x + threadIdx.x;
    if (i >= 6 * DH) return;
    const float* wr = (i < 3 * DH) ? &Wf[(long)i * DH] : &Wb[(long)(i - 3 * DH) * DH];
    float acc = (i < 3 * DH) ? bihf[i] : bihb[i - 3 * DH];
    for (int j = 0; j < DH; j++) acc = fmaf(wr[j], bm[j], acc);
    bc[i] = acc;
}

// ---------------- fp32 -> padded fp16 convert ----------------
__global__ void f2h_pad_kernel(const float* __restrict__ src, __half* __restrict__ dst,
                               long rows, int K, int Kpad)
{
    long n2 = rows * (Kpad / 2);
    long i = (long)blockIdx.x * blockDim.x + threadIdx.x;
    if (i >= n2) return;
    int  c2 = (int)(i % (Kpad / 2));
    long r  = i / (Kpad / 2);
    int col = 2 * c2;
    __half2 h;
    if (col < K) {
        float2 v = *reinterpret_cast<const float2*>(&src[r * K + col]);
        h = __floats2half2_rn(v.x, v.y);
    } else {
        h = __floats2half2_rn(0.f, 0.f);
    }
    *reinterpret_cast<__half2*>(&dst[r * Kpad + col]) = h;
}

// ---------------- gather + mean, padded fp16 out ----------------
__global__ void gather_mean_kernel(const float* __restrict__ nodes,
                                   const int* __restrict__ trip,
                                   __half* __restrict__ out)
{
    long total = (long)M_BT * (P_DN / 2);
    long idx = (long)blockIdx.x * blockDim.x + threadIdx.x;
    if (idx >= total) return;
    int  c2 = (int)(idx % (P_DN / 2));
    long bt = idx / (P_DN / 2);
    int col = 2 * c2;
    int b = (int)(bt / TT);
    __half2 o;
    if (col < DN) {
        int h  = trip[bt * 3 + 0];
        int tl = trip[bt * 3 + 2];
        float2 vh = *reinterpret_cast<const float2*>(&nodes[((long)b * NN + h)  * DN + col]);
        float2 vt = *reinterpret_cast<const float2*>(&nodes[((long)b * NN + tl) * DN + col]);
        o = __floats2half2_rn(0.5f * (vh.x + vt.x), 0.5f * (vh.y + vt.y));
    } else {
        o = __floats2half2_rn(0.f, 0.f);
    }
    *reinterpret_cast<__half2*>(&out[bt * P_DN + col]) = o;
}

// ---------------- GRU gate activation: gi(half) -> hidden(half, padded) ------
__global__ void gru_act2_kernel(const __half* __restrict__ gi,
                                const float* __restrict__ bhf,
                                const float* __restrict__ bhb,
                                __half* __restrict__ hidden)
{
    long total = (long)M_BT * (P_2DH / 2);
    long idx = (long)blockIdx.x * blockDim.x + threadIdx.x;
    if (idx >= total) return;
    int  c2 = (int)(idx % (P_2DH / 2));
    long i  = idx / (P_2DH / 2);
    int col = 2 * c2;
    __half2 res;
    if (col < 2 * DH) {
        int dir = col / DH;
        int j   = col - dir * DH;         // even
        const __half* gg = gi + i * P_6DH + (long)dir * (3 * DH);
        const float*  bh = dir ? bhb : bhf;
        float2 R = __half22float2(*reinterpret_cast<const __half2*>(&gg[j]));
        float2 Z = __half22float2(*reinterpret_cast<const __half2*>(&gg[DH + j]));
        float2 Nv = __half22float2(*reinterpret_cast<const __half2*>(&gg[2 * DH + j]));
        float r0 = 1.f / (1.f + expf(-(R.x + bh[j])));
        float r1 = 1.f / (1.f + expf(-(R.y + bh[j + 1])));
        float z0 = 1.f / (1.f + expf(-(Z.x + bh[DH + j])));
        float z1 = 1.f / (1.f + expf(-(Z.y + bh[DH + j + 1])));
        float n0 = tanhf(Nv.x + r0 * bh[2 * DH + j]);
        float n1 = tanhf(Nv.y + r1 * bh[2 * DH + j + 1]);
        res = __floats2half2_rn((1.f - z0) * n0, (1.f - z1) * n1);
    } else {
        res = __floats2half2_rn(0.f, 0.f);
    }
    *reinterpret_cast<__half2*>(&hidden[i * P_2DH + col]) = res;
}

// ---------------- per-row softmax + atomic alpha accumulation ----------------
__global__ void softmax_row_kernel(const float* __restrict__ S,
                                   float* __restrict__ alpha)
{
    int l = blockIdx.x, b = blockIdx.y;
    int t = threadIdx.x;                 // 0..511
    __shared__ float red[16];
    __shared__ float bcast;
    const float* row = S + ((long)b * LQ + l) * TT;
    float s = row[t];

    float m = s;
    #pragma unroll
    for (int o = 16; o > 0; o >>= 1) m = fmaxf(m, __shfl_xor_sync(0xffffffffu, m, o));
    if ((t & 31) == 0) red[t >> 5] = m;
    __syncthreads();
    if (t < 16) {
        float v = red[t];
        #pragma unroll
        for (int o = 8; o > 0; o >>= 1) v = fmaxf(v, __shfl_xor_sync(0xffffu, v, o));
        if (t == 0) bcast = v;
    }
    __syncthreads();
    float bm = bcast;

    float e = expf(s - bm);
    float sm = e;
    #pragma unroll
    for (int o = 16; o > 0; o >>= 1) sm += __shfl_xor_sync(0xffffffffu, sm, o);
    if ((t & 31) == 0) red[t >> 5] = sm;
    __syncthreads();
    if (t < 16) {
        float v = red[t];
        #pragma unroll
        for (int o = 8; o > 0; o >>= 1) v += __shfl_xor_sync(0xffffu, v, o);
        if (t == 0) bcast = v;
    }
    __syncthreads();
    float tot = bcast;

    atomicAdd(&alpha[(long)b * TT + t], e / tot);
}

// ---------------- rep = alpha @ hid(half), then LayerNorm -> path_feature ------
__global__ void rep_ln_kernel(const __half* __restrict__ hid,
                              const float* __restrict__ alpha,
                              const float* __restrict__ gamma,
                              const float* __restrict__ beta,
                              float* __restrict__ out)
{
    int b = blockIdx.x;
    int tid = threadIdx.x;        // 512
    __shared__ float a_s[TT];
    __shared__ float r_s[DH];
    __shared__ float red[32];
    a_s[tid] = alpha[(long)b * TT + tid];
    __syncthreads();
    if (tid < DH) {
        const __half* hb = hid + (long)b * TT * P_DH;
        float v0 = 0.f, v1 = 0.f, v2 = 0.f, v3 = 0.f;
        #pragma unroll 1
        for (int t = 0; t < TT; t += 4) {
            v0 = fmaf(a_s[t + 0], __half2float(hb[(long)(t + 0) * P_DH + tid]), v0);
            v1 = fmaf(a_s[t + 1], __half2float(hb[(long)(t + 1) * P_DH + tid]), v1);
            v2 = fmaf(a_s[t + 2], __half2float(hb[(long)(t + 2) * P_DH + tid]), v2);
            v3 = fmaf(a_s[t + 3], __half2float(hb[(long)(t + 3) * P_DH + tid]), v3);
        }
        r_s[tid] = (v0 + v1) + (v2 + v3);
    }
    __syncthreads();
    float p  = (tid < DH) ? r_s[tid] : 0.f;
    float p2 = p * p;
    #pragma unroll
    for (int o = 16; o > 0; o >>= 1) {
        p  += __shfl_xor_sync(0xffffffffu, p,  o);
        p2 += __shfl_xor_sync(0xffffffffu, p2, o);
    }
    if ((tid & 31) == 0) { red[tid >> 5] = p; red[16 + (tid >> 5)] = p2; }
    __syncthreads();
    float mean = 0.f, m2 = 0.f;
    #pragma unroll
    for (int w = 0; w < 16; w++) { mean += red[w]; m2 += red[16 + w]; }
    mean /= (float)DH; m2 /= (float)DH;
    float var = m2 - mean * mean;
    if (tid < DH)
        out[(long)b * DH + tid] =
            (r_s[tid] - mean) * rsqrtf(var + EPS) * gamma[tid] + beta[tid];
}

// ---------------- zero-fill ----------------
__global__ void zero_kernel(float* __restrict__ p, long n)
{
    long i = (long)blockIdx.x * blockDim.x + threadIdx.x;
    if (i < n) p[i] = 0.f;
}

// ---------------- host launcher ----------------
extern "C" void kernel_launch(void* const* d_in, const int* in_sizes, int n_in,
                              void* d_out, int out_size)
{
    const float* nodes   = (const float*)d_in[0];
    const float* ctx     = (const float*)d_in[1];
    const int*   trip    = (const int*)  d_in[2];
    // d_in[3] = node_number (compile-time constant NN = 256)
    const float* W_mean  = (const float*)d_in[4];
    const float* b_mean  = (const float*)d_in[5];
    const float* W_ih_f  = (const float*)d_in[6];
    const float* b_ih_f  = (const float*)d_in[7];
    const float* b_hh_f  = (const float*)d_in[8];
    const float* W_ih_b  = (const float*)d_in[9];
    const float* b_ih_b  = (const float*)d_in[10];
    const float* b_hh_b  = (const float*)d_in[11];
    const float* W_out   = (const float*)d_in[12];
    const float* b_out   = (const float*)d_in[13];
    const float* W_node  = (const float*)d_in[14];
    const float* b_node  = (const float*)d_in[15];
    const float* gamma   = (const float*)d_in[16];
    const float* beta    = (const float*)d_in[17];
    float* out = (float*)d_out;

    __half *p_tri, *p_hiddenh, *p_hidh, *p_ctxh, *p_nodesh;
    __half *p_wc, *p_wout, *p_wnode;
    float *p_big, *p_alpha, *p_bc, *p_zb;
    cudaGetSymbolAddress((void**)&p_tri,     g_tri_h);
    cudaGetSymbolAddress((void**)&p_big,     g_big);
    cudaGetSymbolAddress((void**)&p_hiddenh, g_hidden_h);
    cudaGetSymbolAddress((void**)&p_hidh,    g_hid_h);
    cudaGetSymbolAddress((void**)&p_ctxh,    g_ctx_h);
    cudaGetSymbolAddress((void**)&p_nodesh,  g_nodes_h);
    cudaGetSymbolAddress((void**)&p_wc,      g_wc_h);
    cudaGetSymbolAddress((void**)&p_bc,      g_bc);
    cudaGetSymbolAddress((void**)&p_wout,    g_wout_h);
    cudaGetSymbolAddress((void**)&p_wnode,   g_wnode_h);
    cudaGetSymbolAddress((void**)&p_alpha,   g_alpha);
    cudaGetSymbolAddress((void**)&p_zb,      g_zero_bias);

    __half* p_gi     = (__half*)p_big;   // [M_BT, 1808] half, GRU phase
    float*  p_scores = p_big;            // [B, LQ, TT] float, attention phase

    cudaFuncSetAttribute(mma_gemm_kernel<false, true>,
                         cudaFuncAttributeMaxDynamicSharedMemorySize, GEMM_SMEM);
    cudaFuncSetAttribute(mma_gemm_kernel<true, true>,
                         cudaFuncAttributeMaxDynamicSharedMemorySize, GEMM_SMEM);
    cudaFuncSetAttribute(mma_gemm_kernel<false, false>,
                         cudaFuncAttributeMaxDynamicSharedMemorySize, GEMM_SMEM);

    // 0a) fused GRU-input weight/bias: Wc = Wih @ W_mean, bc = Wih@b_mean + b_ih
    {
        int n = 6 * DH * P_DN;
        wc_weight_kernel<<<(n + 255) / 256, 256>>>(W_ih_f, W_ih_b, W_mean, p_wc);
        wc_bias_kernel<<<(6 * DH + 255) / 256, 256>>>(W_ih_f, W_ih_b, b_mean,
                                                      b_ih_f, b_ih_b, p_bc);
    }
    // 0b) operand conversion to padded fp16
    auto conv = [&](const float* s, __half* d, long rows, int K, int Kp) {
        long n2 = rows * (Kp / 2);
        f2h_pad_kernel<<<(unsigned)((n2 + 255) / 256), 256>>>(s, d, rows, K, Kp);
    };
    conv(ctx,    p_ctxh,  (long)BB * LQ, DH, P_DH);
    conv(nodes,  p_nodesh, M_BN, DN, P_DN);
    conv(W_node, p_wnode, DH, DN, P_DN);
    conv(W_out,  p_wout,  DH, 2 * DH, P_2DH);

    // 1) tri_mean gather -> half padded
    {
        long total = (long)M_BT * (P_DN / 2);
        gather_mean_kernel<<<(unsigned)((total + 255) / 256), 256>>>(nodes, trip, p_tri);
    }
    // 2+3 fused) gi = tri_mean @ Wc^T + bc   [65536,1800] Kpad=104 -> half [.,1808]
    {
        dim3 g(15, M_BT / 128, 1);
        mma_gemm_kernel<false, true><<<g, 256, GEMM_SMEM>>>(
            p_tri, p_wc, p_bc, p_gi, M_BT, 6 * DH, P_DN, P_DN, P_DN, P_6DH, 0, 0, 0);
    }
    // 4) gate activation -> hidden half [65536,608]
    {
        long total = (long)M_BT * (P_2DH / 2);
        gru_act2_kernel<<<(unsigned)((total + 255) / 256), 256>>>(p_gi, b_hh_f, b_hh_b, p_hiddenh);
    }
    // 5) hid = tanh(hidden @ W_out^T + b_out)   [65536,300] Kpad=608 -> half [.,304]
    {
        dim3 g(3, M_BT / 128, 1);
        mma_gemm_kernel<true, true><<<g, 256, GEMM_SMEM>>>(
            p_hiddenh, p_wout, b_out, p_hidh, M_BT, DH, P_2DH, P_2DH, P_2DH, P_DH, 0, 0, 0);
    }
    // 6) scores[b] = ctx[b] @ hid[b]^T   (batched M=256,N=512,Kpad=304) -> float
    {
        dim3 g(4, LQ / 128, BB);
        mma_gemm_kernel<false, false><<<g, 256, GEMM_SMEM>>>(
            p_ctxh, p_hidh, p_zb, p_scores, LQ, TT, P_DH, P_DH, P_DH, TT,
            (long)LQ * P_DH, (long)TT * P_DH, (long)LQ * TT);
    }
    // 7) alpha = sum_l softmax_t(scores)
    {
        long an = (long)BB * TT;
        zero_kernel<<<(unsigned)((an + 255) / 256), 256>>>(p_alpha, an);
        dim3 g(LQ, BB);
        softmax_row_kernel<<<g, TT>>>(p_scores, p_alpha);
    }
    // 8) rep + LayerNorm -> path_feature (out offset 0)
    rep_ln_kernel<<<BB, TT>>>(p_hidh, p_alpha, gamma, beta, out);
    // 9) node_feature = nodes @ W_node^T + b_node -> float out at offset B*DH
    {
        dim3 g(3, M_BN / 128, 1);
        mma_gemm_kernel<false, false><<<g, 256, GEMM_SMEM>>>(
            p_nodesh, p_wnode, b_node, out + (long)BB * DH, M_BN, DH, P_DN, P_DN, P_DN, DH,
            0, 0, 0);
    }
    // 10) node_mask zeros, if the output buffer includes it
    {
        long mask_off = (long)BB * DH + (long)M_BN * DH;   // 9,868,800
        long mask_n   = (long)BB * NN;                     // 32,768
        if ((long)out_size >= mask_off + mask_n) {
            zero_kernel<<<(unsigned)((mask_n + 255) / 256), 256>>>(out + mask_off, mask_n);
        }
    }
}